// round 2
// baseline (speedup 1.0000x reference)
#include <cuda_runtime.h>
#include <math.h>

#define BSZ   16
#define NTOT  8208
#define HD    768
#define NG    5
#define NM    96          // 16 q rows + 80 (q*inv_g) rows

// output offsets (flattened concat of the 8 reference outputs, float32)
#define OFF_GLOG 0
#define OFF_GPRB 656640
#define OFF_CLOG 1313280
#define OFF_ACC  1444608
#define OFF_NRM  1575936
#define OFF_GLBL 1575941
#define OFF_CLBL 1707269
#define OFF_CDST 1838597

__device__ float g_W[NM * HD];
__device__ float g_inv[NG * HD];
__device__ float g_muinv[NG * HD];
__device__ float g_Cbg[BSZ * NG];
__device__ float g_SaaSam[NTOT * 10];
__device__ float g_S[NM * NTOT];
__device__ unsigned g_rowmax_u[BSZ];
__device__ float g_cnt[NG];
__device__ float g_sum[NG];

typedef unsigned long long u64;

__device__ __forceinline__ u64 fma2(u64 a, u64 b, u64 c) {
    u64 d;
    asm("fma.rn.f32x2 %0, %1, %2, %3;" : "=l"(d) : "l"(a), "l"(b), "l"(c));
    return d;
}
__device__ __forceinline__ u64 mul2(u64 a, u64 b) {
    u64 d;
    asm("mul.rn.f32x2 %0, %1, %2;" : "=l"(d) : "l"(a), "l"(b));
    return d;
}
__device__ __forceinline__ float2 upk(u64 u) {
    float2 r;
    asm("mov.b64 {%0,%1}, %2;" : "=f"(r.x), "=f"(r.y) : "l"(u));
    return r;
}

__device__ __forceinline__ float wred(float v) {
    #pragma unroll
    for (int o = 16; o; o >>= 1) v += __shfl_down_sync(0xffffffffu, v, o);
    return v;
}

__device__ __forceinline__ unsigned fenc(float f) {
    unsigned b = __float_as_uint(f);
    return (b & 0x80000000u) ? ~b : (b | 0x80000000u);
}
__device__ __forceinline__ float fdec(unsigned u) {
    return (u & 0x80000000u) ? __uint_as_float(u ^ 0x80000000u)
                             : __uint_as_float(~u);
}

// ---------------------------------------------------------------------------
// K1: inv = exp(-lgs); muinv = mu*inv; init accumulators/rowmax
// ---------------------------------------------------------------------------
__global__ void inv_kernel(const float* __restrict__ mu,
                           const float* __restrict__ lgs) {
    int i = blockIdx.x * 256 + threadIdx.x;
    if (i < NG * HD) {
        float v = expf(-lgs[i]);
        g_inv[i]   = v;
        g_muinv[i] = mu[i] * v;
    }
    if (blockIdx.x == 0 && threadIdx.x < 32) {
        if (threadIdx.x < NG)  { g_cnt[threadIdx.x] = 0.f; g_sum[threadIdx.x] = 0.f; }
        if (threadIdx.x < BSZ) g_rowmax_u[threadIdx.x] = 0u;
    }
}

// ---------------------------------------------------------------------------
// K2: build W = [q rows ; q*inv_g rows]  (96 x 768)
// ---------------------------------------------------------------------------
__global__ void w_kernel(const float* __restrict__ q) {
    int i = blockIdx.x * 256 + threadIdx.x;
    if (i >= NM * HD) return;
    int m = i / HD, h = i - m * HD;
    float w;
    if (m < BSZ) w = q[m * HD + h];
    else {
        int bg = m - BSZ;
        int b = bg / NG, g = bg - b * NG;
        w = q[b * HD + h] * g_inv[g * HD + h];
    }
    g_W[i] = w;
}

// ---------------------------------------------------------------------------
// K3: per-(b,g) constants Cbg   (one warp per (b,g), 80 warps)
// ---------------------------------------------------------------------------
__global__ void cbg_kernel(const float* __restrict__ q,
                           const float* __restrict__ mu,
                           const float* __restrict__ lgs,
                           const float* __restrict__ pi) {
    int job = blockIdx.x * 8 + (threadIdx.x >> 5);
    int lane = threadIdx.x & 31;
    if (job >= BSZ * NG) return;
    int b = job / NG, g = job - b * NG;

    float a1 = 0.f, a2 = 0.f;
    for (int h = lane; h < HD; h += 32) {
        float iv = g_inv[g * HD + h];
        float mv = g_muinv[g * HD + h];
        float qv = q[b * HD + h];
        float m_ = mu[g * HD + h];
        a1 += lgs[g * HD + h] + qv * qv * iv + m_ * mv;
        a2 += qv * mv;
    }
    a1 = wred(a1); a2 = wred(a2);
    if (lane == 0) {
        // log_softmax(pi)[g]
        float m = pi[0];
        #pragma unroll
        for (int i = 1; i < NG; i++) m = fmaxf(m, pi[i]);
        float s = 0.f;
        #pragma unroll
        for (int i = 0; i < NG; i++) s += expf(pi[i] - m);
        float lse = m + logf(s);
        const float LG2PID = 768.0f * 1.8378770351409912f;
        g_Cbg[job] = (pi[g] - lse) - 0.5f * (LG2PID + a1) + a2;
    }
}

// ---------------------------------------------------------------------------
// K4: per-n Saa[g], Sam[g] — inv/muinv cached in smem, packed f32x2 FMAs
//     1 warp per n, 8 n per block
// ---------------------------------------------------------------------------
__global__ __launch_bounds__(256) void saasam_kernel(const float* __restrict__ sk,
                                                     const float* __restrict__ qu) {
    __shared__ float s_inv[NG * HD];
    __shared__ float s_mu[NG * HD];
    const int tid = threadIdx.x;
    for (int i = tid; i < NG * HD; i += 256) {
        s_inv[i] = g_inv[i];
        s_mu[i]  = g_muinv[i];
    }
    __syncthreads();

    const int warp = tid >> 5, lane = tid & 31;
    const int n = blockIdx.x * 8 + warp;           // grid exact: 1026*8 = 8208
    const float* a = (n < BSZ) ? (sk + n * HD) : (qu + (n - BSZ) * HD);
    const u64* a2 = (const u64*)a;
    const u64* iv2 = (const u64*)s_inv;
    const u64* mv2 = (const u64*)s_mu;

    u64 saa[NG] = {0, 0, 0, 0, 0}, sam[NG] = {0, 0, 0, 0, 0};
    #pragma unroll
    for (int it = 0; it < HD / 64; it++) {
        int p = lane + it * 32;                    // float2 index within row
        u64 av = a2[p];
        u64 v2 = mul2(av, av);
        #pragma unroll
        for (int g = 0; g < NG; g++) {
            saa[g] = fma2(v2, iv2[g * (HD / 2) + p], saa[g]);
            sam[g] = fma2(av, mv2[g * (HD / 2) + p], sam[g]);
        }
    }
    float r[10];
    #pragma unroll
    for (int g = 0; g < NG; g++) {
        float2 x = upk(saa[g]); r[g] = x.x + x.y;
        float2 y = upk(sam[g]); r[5 + g] = y.x + y.y;
    }
    #pragma unroll
    for (int i = 0; i < 10; i++) r[i] = wred(r[i]);
    if (lane == 0) {
        #pragma unroll
        for (int i = 0; i < 10; i++) g_SaaSam[n * 10 + i] = r[i];
    }
}

// ---------------------------------------------------------------------------
// K5: SGEMM  g_S[96][8208] = g_W @ all_feature^T, packed f32x2 FMAs
//     BM=96 (full), BN=64, BK=16, 256 thr, 6x4 tile packed over rows.
//     Also computes rowmax of the first 16 rows via atomicMax.
// ---------------------------------------------------------------------------
#define BKk 16
#define ASTR 100
#define BSTR 132

__global__ __launch_bounds__(256) void gemm_kernel(const float* __restrict__ sk,
                                                   const float* __restrict__ qu) {
    __shared__ float As[BKk * ASTR];
    __shared__ float Bs[BKk * BSTR];               // duplicated columns
    const int tid = threadIdx.x;
    const int n0  = blockIdx.x * 64;
    const int tr  = tid >> 4;                      // 0..15 -> rows tr*6..+5
    const int tc  = tid & 15;                      // 0..15 -> cols tc*4..+3

    u64 acc[3][4];
    #pragma unroll
    for (int i = 0; i < 3; i++)
        #pragma unroll
        for (int j = 0; j < 4; j++) acc[i][j] = 0ull;

    float pa[6], pb[4];
    #pragma unroll
    for (int j = 0; j < 6; j++) {
        int e = tid + j * 256; int k = e & 15, m = e >> 4;
        pa[j] = g_W[m * HD + k];
    }
    #pragma unroll
    for (int j = 0; j < 4; j++) {
        int e = tid + j * 256; int k = e & 15, n = e >> 4;
        int gn = n0 + n;
        float v = 0.f;
        if (gn < NTOT) {
            const float* src = (gn < BSZ) ? (sk + gn * HD) : (qu + (gn - BSZ) * HD);
            v = src[k];
        }
        pb[j] = v;
    }

    for (int s = 0; s < HD / BKk; s++) {
        #pragma unroll
        for (int j = 0; j < 6; j++) {
            int e = tid + j * 256; int k = e & 15, m = e >> 4;
            As[k * ASTR + m] = pa[j];
        }
        #pragma unroll
        for (int j = 0; j < 4; j++) {
            int e = tid + j * 256; int k = e & 15, n = e >> 4;
            Bs[k * BSTR + 2 * n]     = pb[j];
            Bs[k * BSTR + 2 * n + 1] = pb[j];
        }
        __syncthreads();

        if (s < HD / BKk - 1) {
            int k0 = (s + 1) * BKk;
            #pragma unroll
            for (int j = 0; j < 6; j++) {
                int e = tid + j * 256; int k = e & 15, m = e >> 4;
                pa[j] = g_W[m * HD + k0 + k];
            }
            #pragma unroll
            for (int j = 0; j < 4; j++) {
                int e = tid + j * 256; int k = e & 15, n = e >> 4;
                int gn = n0 + n;
                float v = 0.f;
                if (gn < NTOT) {
                    const float* src = (gn < BSZ) ? (sk + gn * HD) : (qu + (gn - BSZ) * HD);
                    v = src[k0 + k];
                }
                pb[j] = v;
            }
        }

        #pragma unroll
        for (int k = 0; k < BKk; k++) {
            const float* ar = &As[k * ASTR + tr * 6];
            const float* br = &Bs[k * BSTR + tc * 8];
            u64 ap0 = *(const u64*)(ar);
            u64 ap1 = *(const u64*)(ar + 2);
            u64 ap2 = *(const u64*)(ar + 4);
            u64 bp0 = *(const u64*)(br);
            u64 bp1 = *(const u64*)(br + 2);
            u64 bp2 = *(const u64*)(br + 4);
            u64 bp3 = *(const u64*)(br + 6);
            acc[0][0] = fma2(ap0, bp0, acc[0][0]);
            acc[0][1] = fma2(ap0, bp1, acc[0][1]);
            acc[0][2] = fma2(ap0, bp2, acc[0][2]);
            acc[0][3] = fma2(ap0, bp3, acc[0][3]);
            acc[1][0] = fma2(ap1, bp0, acc[1][0]);
            acc[1][1] = fma2(ap1, bp1, acc[1][1]);
            acc[1][2] = fma2(ap1, bp2, acc[1][2]);
            acc[1][3] = fma2(ap1, bp3, acc[1][3]);
            acc[2][0] = fma2(ap2, bp0, acc[2][0]);
            acc[2][1] = fma2(ap2, bp1, acc[2][1]);
            acc[2][2] = fma2(ap2, bp2, acc[2][2]);
            acc[2][3] = fma2(ap2, bp3, acc[2][3]);
        }
        __syncthreads();
    }

    const int nbase = n0 + tc * 4;
    if (nbase < NTOT) {                            // tail is a multiple of 4
        #pragma unroll
        for (int ip = 0; ip < 3; ip++) {
            float2 r0 = upk(acc[ip][0]);
            float2 r1 = upk(acc[ip][1]);
            float2 r2 = upk(acc[ip][2]);
            float2 r3 = upk(acc[ip][3]);
            int m0 = tr * 6 + 2 * ip;
            float4 lo = make_float4(r0.x, r1.x, r2.x, r3.x);
            float4 hi = make_float4(r0.y, r1.y, r2.y, r3.y);
            *(float4*)&g_S[(size_t)m0 * NTOT + nbase]       = lo;
            *(float4*)&g_S[(size_t)(m0 + 1) * NTOT + nbase] = hi;
            if (m0 < BSZ) {
                float mx = fmaxf(fmaxf(lo.x, lo.y), fmaxf(lo.z, lo.w));
                atomicMax(&g_rowmax_u[m0], fenc(mx));
            }
            if (m0 + 1 < BSZ) {
                float mx = fmaxf(fmaxf(hi.x, hi.y), fmaxf(hi.z, hi.w));
                atomicMax(&g_rowmax_u[m0 + 1], fenc(mx));
            }
        }
    }
}

// ---------------------------------------------------------------------------
// K6: fused epilogue over all (b, n) cells
// ---------------------------------------------------------------------------
__global__ __launch_bounds__(256) void epi_kernel(const float* __restrict__ rank_mean,
                                                  float* __restrict__ out) {
    __shared__ float s_cnt[NG], s_sum[NG];
    const int tid = threadIdx.x;
    if (tid < NG) { s_cnt[tid] = 0.f; s_sum[tid] = 0.f; }
    __syncthreads();

    const int idx = blockIdx.x * 256 + tid;        // grid sized exactly
    const int b = idx / NTOT;
    const int n = idx - b * NTOT;

    const float sim = g_S[b * NTOT + n];

    float lg[NG], ev[NG];
    #pragma unroll
    for (int g = 0; g < NG; g++) {
        float Sqa = g_S[(size_t)(BSZ + b * NG + g) * NTOT + n];
        float Saa = g_SaaSam[n * 10 + g];
        float Sam = g_SaaSam[n * 10 + 5 + g];
        lg[g] = g_Cbg[b * NG + g] + Sqa - 0.5f * Saa - Sam;
    }
    float m = lg[0]; int bi = 0;
    #pragma unroll
    for (int g = 1; g < NG; g++) if (lg[g] > m) { m = lg[g]; bi = g; }

    float sum = 0.f;
    #pragma unroll
    for (int g = 0; g < NG; g++) {
        float ln = lg[g] - m;
        out[OFF_GLOG + (size_t)idx * NG + g] = ln;
        float e = __expf(ln);
        ev[g] = e; sum += e;
    }
    float isum = 1.f / sum;
    #pragma unroll
    for (int g = 0; g < NG; g++)
        out[OFF_GPRB + (size_t)idx * NG + g] = ev[g] * isum;

    float bd = fabsf(sim - rank_mean[0]); int cp = 0;
    #pragma unroll
    for (int g = 1; g < NG; g++) {
        float d = fabsf(sim - rank_mean[g]);
        if (d < bd) { bd = d; cp = g; }
    }
    int cd = (int)floorf((sim + 1.0f) / 2.0f * 5.0f);

    bool golden = (n < BSZ) && (n == ((b + 8) & 15));
    bool eye    = (n == b);

    out[OFF_CLOG + idx] = sim - fdec(g_rowmax_u[b]);
    out[OFF_ACC  + idx] = eye ? 0.f : sim;
    out[OFF_GLBL + idx] = (float)((eye || golden) ? (NG - 1) : cp);
    out[OFF_CLBL + idx] = (float)(golden ? (NG - 1) : bi);
    out[OFF_CDST + idx] = (float)cd;

    atomicAdd(&s_cnt[bi], 1.f);
    atomicAdd(&s_sum[bi], sim);
    __syncthreads();
    if (tid < NG) {
        atomicAdd(&g_cnt[tid], s_cnt[tid]);
        atomicAdd(&g_sum[tid], s_sum[tid]);
    }
}

// ---------------------------------------------------------------------------
// K7: rank-mean EMA finalize
// ---------------------------------------------------------------------------
__global__ void finish_kernel(const float* __restrict__ rank_mean,
                              float* __restrict__ out) {
    int g = threadIdx.x;
    if (g < NG) {
        float c = g_cnt[g], s = g_sum[g];
        float cur = s / (c + 1e-12f);
        float upd = (c != 0.f) ? 1.f : 0.f;
        out[OFF_NRM + g] = (1.f - upd * 0.1f) * rank_mean[g] + upd * 0.1f * cur;
    }
}

// ---------------------------------------------------------------------------
extern "C" void kernel_launch(void* const* d_in, const int* in_sizes, int n_in,
                              void* d_out, int out_size) {
    const float* sent_q    = (const float*)d_in[0];
    const float* sent_k    = (const float*)d_in[1];
    const float* queue     = (const float*)d_in[2];
    const float* mu        = (const float*)d_in[3];
    const float* lg_sigma2 = (const float*)d_in[4];
    const float* pi        = (const float*)d_in[5];
    const float* rank_mean = (const float*)d_in[6];
    float* out = (float*)d_out;

    inv_kernel<<<(NG * HD + 255) / 256, 256>>>(mu, lg_sigma2);
    w_kernel<<<(NM * HD + 255) / 256, 256>>>(sent_q);
    cbg_kernel<<<10, 256>>>(sent_q, mu, lg_sigma2, pi);
    saasam_kernel<<<NTOT / 8, 256>>>(sent_k, queue);
    gemm_kernel<<<(NTOT + 63) / 64, 256>>>(sent_k, queue);
    epi_kernel<<<(BSZ * NTOT) / 256, 256>>>(rank_mean, out);
    finish_kernel<<<1, 32>>>(rank_mean, out);
}

// round 3
// speedup vs baseline: 1.1087x; 1.1087x over previous
#include <cuda_runtime.h>
#include <math.h>

#define BSZ   16
#define NTOT  8208
#define HD    768
#define NG    5
#define NM    96          // 16 q rows + 80 (q*inv_g) rows

// output offsets (flattened concat of the 8 reference outputs, float32)
#define OFF_GLOG 0
#define OFF_GPRB 656640
#define OFF_CLOG 1313280
#define OFF_ACC  1444608
#define OFF_NRM  1575936
#define OFF_GLBL 1575941
#define OFF_CLBL 1707269
#define OFF_CDST 1838597

__device__ float g_W[NM * HD];
__device__ float g_inv[NG * HD];
__device__ float g_muinv[NG * HD];
__device__ float g_Cbg[BSZ * NG];
__device__ float g_SaaSam[NTOT * 10];
__device__ float g_S[NM * NTOT];
__device__ unsigned g_rowmax_u[BSZ];
__device__ float g_cnt[NG];
__device__ float g_sum[NG];

typedef unsigned long long u64;

__device__ __forceinline__ u64 fma2(u64 a, u64 b, u64 c) {
    u64 d;
    asm("fma.rn.f32x2 %0, %1, %2, %3;" : "=l"(d) : "l"(a), "l"(b), "l"(c));
    return d;
}
__device__ __forceinline__ u64 mul2(u64 a, u64 b) {
    u64 d;
    asm("mul.rn.f32x2 %0, %1, %2;" : "=l"(d) : "l"(a), "l"(b));
    return d;
}
__device__ __forceinline__ u64 pk2(float x, float y) {
    u64 d;
    asm("mov.b64 %0, {%1,%2};" : "=l"(d) : "f"(x), "f"(y));
    return d;
}
__device__ __forceinline__ float2 upk(u64 u) {
    float2 r;
    asm("mov.b64 {%0,%1}, %2;" : "=f"(r.x), "=f"(r.y) : "l"(u));
    return r;
}

__device__ __forceinline__ float wred(float v) {
    #pragma unroll
    for (int o = 16; o; o >>= 1) v += __shfl_down_sync(0xffffffffu, v, o);
    return v;
}

__device__ __forceinline__ unsigned fenc(float f) {
    unsigned b = __float_as_uint(f);
    return (b & 0x80000000u) ? ~b : (b | 0x80000000u);
}
__device__ __forceinline__ float fdec(unsigned u) {
    return (u & 0x80000000u) ? __uint_as_float(u ^ 0x80000000u)
                             : __uint_as_float(~u);
}

// ---------------------------------------------------------------------------
// K1: inv = exp(-lgs); muinv = mu*inv; init accumulators/rowmax
// ---------------------------------------------------------------------------
__global__ void inv_kernel(const float* __restrict__ mu,
                           const float* __restrict__ lgs) {
    int i = blockIdx.x * 256 + threadIdx.x;
    if (i < NG * HD) {
        float v = expf(-lgs[i]);
        g_inv[i]   = v;
        g_muinv[i] = mu[i] * v;
    }
    if (blockIdx.x == 0 && threadIdx.x < 32) {
        if (threadIdx.x < NG)  { g_cnt[threadIdx.x] = 0.f; g_sum[threadIdx.x] = 0.f; }
        if (threadIdx.x < BSZ) g_rowmax_u[threadIdx.x] = 0u;
    }
}

// ---------------------------------------------------------------------------
// K2: build W = [q rows ; q*inv_g rows]  (96 x 768)
// ---------------------------------------------------------------------------
__global__ void w_kernel(const float* __restrict__ q) {
    int i = blockIdx.x * 256 + threadIdx.x;
    if (i >= NM * HD) return;
    int m = i / HD, h = i - m * HD;
    float w;
    if (m < BSZ) w = q[m * HD + h];
    else {
        int bg = m - BSZ;
        int b = bg / NG, g = bg - b * NG;
        w = q[b * HD + h] * g_inv[g * HD + h];
    }
    g_W[i] = w;
}

// ---------------------------------------------------------------------------
// K3: per-(b,g) constants Cbg   (one warp per (b,g), 80 warps)
// ---------------------------------------------------------------------------
__global__ void cbg_kernel(const float* __restrict__ q,
                           const float* __restrict__ mu,
                           const float* __restrict__ lgs,
                           const float* __restrict__ pi) {
    int job = blockIdx.x * 8 + (threadIdx.x >> 5);
    int lane = threadIdx.x & 31;
    if (job >= BSZ * NG) return;
    int b = job / NG, g = job - b * NG;

    float a1 = 0.f, a2 = 0.f;
    for (int h = lane; h < HD; h += 32) {
        float iv = g_inv[g * HD + h];
        float mv = g_muinv[g * HD + h];
        float qv = q[b * HD + h];
        float m_ = mu[g * HD + h];
        a1 += lgs[g * HD + h] + qv * qv * iv + m_ * mv;
        a2 += qv * mv;
    }
    a1 = wred(a1); a2 = wred(a2);
    if (lane == 0) {
        float m = pi[0];
        #pragma unroll
        for (int i = 1; i < NG; i++) m = fmaxf(m, pi[i]);
        float s = 0.f;
        #pragma unroll
        for (int i = 0; i < NG; i++) s += expf(pi[i] - m);
        float lse = m + logf(s);
        const float LG2PID = 768.0f * 1.8378770351409912f;
        g_Cbg[job] = (pi[g] - lse) - 0.5f * (LG2PID + a1) + a2;
    }
}

// ---------------------------------------------------------------------------
// K4: fused SGEMM + Saa/Sam.
//   g_S[96][8208] = g_W @ all_feature^T  (packed f32x2, row-pair accumulators)
//   g_SaaSam[n][10] accumulated from the same B elements (loaded once).
//   rowmax of first 16 rows via atomicMax.
//   BM=96 (full), BN=64, BK=16, 256 thr.
//   B-loader: thread t owns column nl=t>>2, k-slice kq=(t&3)*4 (float4/tile).
//   Bs duplicated with swizzle: column n at word 2n + 2*(n>>4) (16 distinct
//   banks across tc) — fixes R2's 4-way conflict.
// ---------------------------------------------------------------------------
#define BKk 16
#define ASTR 100
#define BSTR 138

__global__ __launch_bounds__(256) void gemm_kernel(const float* __restrict__ sk,
                                                   const float* __restrict__ qu) {
    __shared__ float As[BKk * ASTR];
    __shared__ float Bs[BKk * BSTR];
    __shared__ float s_inv[NG * HD];
    __shared__ float s_mu[NG * HD];

    const int tid = threadIdx.x;
    const int n0  = blockIdx.x * 64;

    for (int i = tid; i < NG * HD; i += 256) {
        s_inv[i] = g_inv[i];
        s_mu[i]  = g_muinv[i];
    }

    // B loader mapping: one column per thread, 4 k per tile
    const int nl = tid >> 2;                 // 0..63
    const int kq = (tid & 3) * 4;            // 0,4,8,12
    const int gn = n0 + nl;
    const bool bvalid = gn < NTOT;
    const float* bsrc = bvalid ? ((gn < BSZ) ? (sk + gn * HD)
                                             : (qu + (size_t)(gn - BSZ) * HD))
                               : sk;          // dummy, never dereferenced
    const int wB = 2 * nl + 2 * (nl >> 4);   // swizzled dup word offset

    const int tr = tid >> 4;                 // rows tr*6..+5
    const int tc = tid & 15;                 // cols tc*4..+3
    const int bBase = tc * 8 + 2 * (tc >> 2);

    u64 acc[3][4];
    #pragma unroll
    for (int i = 0; i < 3; i++)
        #pragma unroll
        for (int j = 0; j < 4; j++) acc[i][j] = 0ull;
    u64 saa[NG] = {0, 0, 0, 0, 0}, sam[NG] = {0, 0, 0, 0, 0};

    float pa[6];
    float4 pb;
    #pragma unroll
    for (int j = 0; j < 6; j++) {
        int e = tid + j * 256; int k = e & 15, m = e >> 4;
        pa[j] = g_W[m * HD + k];
    }
    pb = bvalid ? *(const float4*)(bsrc + kq) : make_float4(0.f, 0.f, 0.f, 0.f);

    for (int s = 0; s < HD / BKk; s++) {
        #pragma unroll
        for (int j = 0; j < 6; j++) {
            int e = tid + j * 256; int k = e & 15, m = e >> 4;
            As[k * ASTR + m] = pa[j];
        }
        {
            float v[4] = {pb.x, pb.y, pb.z, pb.w};
            #pragma unroll
            for (int i = 0; i < 4; i++)
                *(float2*)&Bs[(kq + i) * BSTR + wB] = make_float2(v[i], v[i]);
        }
        __syncthreads();

        // fused Saa/Sam accumulation on this thread's 4 B elements
        {
            int kk = s * BKk + kq;
            u64 vlo = pk2(pb.x, pb.y), vhi = pk2(pb.z, pb.w);
            u64 qlo = mul2(vlo, vlo),  qhi = mul2(vhi, vhi);
            #pragma unroll
            for (int g = 0; g < NG; g++) {
                const u64* ip = (const u64*)&s_inv[g * HD + kk];
                const u64* mp = (const u64*)&s_mu[g * HD + kk];
                saa[g] = fma2(qlo, ip[0], saa[g]);
                saa[g] = fma2(qhi, ip[1], saa[g]);
                sam[g] = fma2(vlo, mp[0], sam[g]);
                sam[g] = fma2(vhi, mp[1], sam[g]);
            }
        }

        if (s < HD / BKk - 1) {
            int k0 = (s + 1) * BKk;
            #pragma unroll
            for (int j = 0; j < 6; j++) {
                int e = tid + j * 256; int k = e & 15, m = e >> 4;
                pa[j] = g_W[m * HD + k0 + k];
            }
            pb = bvalid ? *(const float4*)(bsrc + k0 + kq)
                        : make_float4(0.f, 0.f, 0.f, 0.f);
        }

        #pragma unroll
        for (int k = 0; k < BKk; k++) {
            const float* ar = &As[k * ASTR + tr * 6];
            const float* br = &Bs[k * BSTR + bBase];
            u64 ap0 = *(const u64*)(ar);
            u64 ap1 = *(const u64*)(ar + 2);
            u64 ap2 = *(const u64*)(ar + 4);
            u64 bp0 = *(const u64*)(br);
            u64 bp1 = *(const u64*)(br + 2);
            u64 bp2 = *(const u64*)(br + 4);
            u64 bp3 = *(const u64*)(br + 6);
            acc[0][0] = fma2(ap0, bp0, acc[0][0]);
            acc[0][1] = fma2(ap0, bp1, acc[0][1]);
            acc[0][2] = fma2(ap0, bp2, acc[0][2]);
            acc[0][3] = fma2(ap0, bp3, acc[0][3]);
            acc[1][0] = fma2(ap1, bp0, acc[1][0]);
            acc[1][1] = fma2(ap1, bp1, acc[1][1]);
            acc[1][2] = fma2(ap1, bp2, acc[1][2]);
            acc[1][3] = fma2(ap1, bp3, acc[1][3]);
            acc[2][0] = fma2(ap2, bp0, acc[2][0]);
            acc[2][1] = fma2(ap2, bp1, acc[2][1]);
            acc[2][2] = fma2(ap2, bp2, acc[2][2]);
            acc[2][3] = fma2(ap2, bp3, acc[2][3]);
        }
        __syncthreads();
    }

    // ---- Saa/Sam reduction across the 4 lanes sharing column nl ----
    {
        float r[10];
        #pragma unroll
        for (int g = 0; g < NG; g++) {
            float2 x = upk(saa[g]); r[g]     = x.x + x.y;
            float2 y = upk(sam[g]); r[5 + g] = y.x + y.y;
        }
        #pragma unroll
        for (int i = 0; i < 10; i++) {
            r[i] += __shfl_xor_sync(0xffffffffu, r[i], 1);
            r[i] += __shfl_xor_sync(0xffffffffu, r[i], 2);
        }
        if (bvalid && (tid & 3) == 0) {
            #pragma unroll
            for (int i = 0; i < 10; i++) g_SaaSam[gn * 10 + i] = r[i];
        }
    }

    // ---- GEMM epilogue + rowmax ----
    const int nbase = n0 + tc * 4;
    if (nbase < NTOT) {
        #pragma unroll
        for (int ip = 0; ip < 3; ip++) {
            float2 r0 = upk(acc[ip][0]);
            float2 r1 = upk(acc[ip][1]);
            float2 r2 = upk(acc[ip][2]);
            float2 r3 = upk(acc[ip][3]);
            int m0 = tr * 6 + 2 * ip;
            float4 lo = make_float4(r0.x, r1.x, r2.x, r3.x);
            float4 hi = make_float4(r0.y, r1.y, r2.y, r3.y);
            *(float4*)&g_S[(size_t)m0 * NTOT + nbase]       = lo;
            *(float4*)&g_S[(size_t)(m0 + 1) * NTOT + nbase] = hi;
            if (m0 < BSZ) {
                float mx = fmaxf(fmaxf(lo.x, lo.y), fmaxf(lo.z, lo.w));
                atomicMax(&g_rowmax_u[m0], fenc(mx));
            }
            if (m0 + 1 < BSZ) {
                float mx = fmaxf(fmaxf(hi.x, hi.y), fmaxf(hi.z, hi.w));
                atomicMax(&g_rowmax_u[m0 + 1], fenc(mx));
            }
        }
    }
}

// ---------------------------------------------------------------------------
// K5: fused epilogue over all (b, n) cells
// ---------------------------------------------------------------------------
__global__ __launch_bounds__(256) void epi_kernel(const float* __restrict__ rank_mean,
                                                  float* __restrict__ out) {
    __shared__ float s_cnt[NG], s_sum[NG];
    const int tid = threadIdx.x;
    if (tid < NG) { s_cnt[tid] = 0.f; s_sum[tid] = 0.f; }
    __syncthreads();

    const int idx = blockIdx.x * 256 + tid;        // grid sized exactly
    const int b = idx / NTOT;
    const int n = idx - b * NTOT;

    const float sim = g_S[b * NTOT + n];

    float lg[NG], ev[NG];
    #pragma unroll
    for (int g = 0; g < NG; g++) {
        float Sqa = g_S[(size_t)(BSZ + b * NG + g) * NTOT + n];
        float Saa = g_SaaSam[n * 10 + g];
        float Sam = g_SaaSam[n * 10 + 5 + g];
        lg[g] = g_Cbg[b * NG + g] + Sqa - 0.5f * Saa - Sam;
    }
    float m = lg[0]; int bi = 0;
    #pragma unroll
    for (int g = 1; g < NG; g++) if (lg[g] > m) { m = lg[g]; bi = g; }

    float sum = 0.f;
    #pragma unroll
    for (int g = 0; g < NG; g++) {
        float ln = lg[g] - m;
        out[OFF_GLOG + (size_t)idx * NG + g] = ln;
        float e = __expf(ln);
        ev[g] = e; sum += e;
    }
    float isum = 1.f / sum;
    #pragma unroll
    for (int g = 0; g < NG; g++)
        out[OFF_GPRB + (size_t)idx * NG + g] = ev[g] * isum;

    float bd = fabsf(sim - rank_mean[0]); int cp = 0;
    #pragma unroll
    for (int g = 1; g < NG; g++) {
        float d = fabsf(sim - rank_mean[g]);
        if (d < bd) { bd = d; cp = g; }
    }
    int cd = (int)floorf((sim + 1.0f) / 2.0f * 5.0f);

    bool golden = (n < BSZ) && (n == ((b + 8) & 15));
    bool eye    = (n == b);

    out[OFF_CLOG + idx] = sim - fdec(g_rowmax_u[b]);
    out[OFF_ACC  + idx] = eye ? 0.f : sim;
    out[OFF_GLBL + idx] = (float)((eye || golden) ? (NG - 1) : cp);
    out[OFF_CLBL + idx] = (float)(golden ? (NG - 1) : bi);
    out[OFF_CDST + idx] = (float)cd;

    atomicAdd(&s_cnt[bi], 1.f);
    atomicAdd(&s_sum[bi], sim);
    __syncthreads();
    if (tid < NG) {
        atomicAdd(&g_cnt[tid], s_cnt[tid]);
        atomicAdd(&g_sum[tid], s_sum[tid]);
    }
}

// ---------------------------------------------------------------------------
// K6: rank-mean EMA finalize
// ---------------------------------------------------------------------------
__global__ void finish_kernel(const float* __restrict__ rank_mean,
                              float* __restrict__ out) {
    int g = threadIdx.x;
    if (g < NG) {
        float c = g_cnt[g], s = g_sum[g];
        float cur = s / (c + 1e-12f);
        float upd = (c != 0.f) ? 1.f : 0.f;
        out[OFF_NRM + g] = (1.f - upd * 0.1f) * rank_mean[g] + upd * 0.1f * cur;
    }
}

// ---------------------------------------------------------------------------
extern "C" void kernel_launch(void* const* d_in, const int* in_sizes, int n_in,
                              void* d_out, int out_size) {
    const float* sent_q    = (const float*)d_in[0];
    const float* sent_k    = (const float*)d_in[1];
    const float* queue     = (const float*)d_in[2];
    const float* mu        = (const float*)d_in[3];
    const float* lg_sigma2 = (const float*)d_in[4];
    const float* pi        = (const float*)d_in[5];
    const float* rank_mean = (const float*)d_in[6];
    float* out = (float*)d_out;

    inv_kernel<<<(NG * HD + 255) / 256, 256>>>(mu, lg_sigma2);
    w_kernel<<<(NM * HD + 255) / 256, 256>>>(sent_q);
    cbg_kernel<<<10, 256>>>(sent_q, mu, lg_sigma2, pi);
    gemm_kernel<<<(NTOT + 63) / 64, 256>>>(sent_k, queue);
    epi_kernel<<<(BSZ * NTOT) / 256, 256>>>(rank_mean, out);
    finish_kernel<<<1, 32>>>(rank_mean, out);
}

// round 5
// speedup vs baseline: 1.6848x; 1.5196x over previous
#include <cuda_runtime.h>
#include <cuda_bf16.h>
#include <math.h>
#include <stdint.h>

#define BSZ   16
#define NTOT  8208
#define HD    768
#define NG    5
#define NM    96

// output offsets (flattened concat of the 8 reference outputs, float32)
#define OFF_GLOG 0
#define OFF_GPRB 656640
#define OFF_CLOG 1313280
#define OFF_ACC  1444608
#define OFF_NRM  1575936
#define OFF_GLBL 1575941
#define OFF_CLBL 1707269
#define OFF_CDST 1838597

__device__ float g_inv[NG * HD];
__device__ float g_muinv[NG * HD];
__device__ __nv_bfloat16 g_W2h[128 * HD];
__device__ __nv_bfloat16 g_W2l[128 * HD];
__device__ float g_Cbg[BSZ * NG];
__device__ float g_SaaSam[NTOT * 10];
__device__ float g_S[NM * NTOT];
__device__ unsigned g_rowmax_u[BSZ];
__device__ float g_cnt[NG];
__device__ float g_sum[NG];

__device__ __forceinline__ float wred(float v) {
    #pragma unroll
    for (int o = 16; o; o >>= 1) v += __shfl_down_sync(0xffffffffu, v, o);
    return v;
}
__device__ __forceinline__ unsigned fenc(float f) {
    unsigned b = __float_as_uint(f);
    return (b & 0x80000000u) ? ~b : (b | 0x80000000u);
}
__device__ __forceinline__ float fdec(unsigned u) {
    return (u & 0x80000000u) ? __uint_as_float(u ^ 0x80000000u)
                             : __uint_as_float(~u);
}

// ---------------------------------------------------------------------------
// mma.sync / ldmatrix / cp.async helpers (plain sm_80+ — compiles for sm_103)
// ---------------------------------------------------------------------------
__device__ __forceinline__ uint32_t smem_u32(const void* p) {
    uint32_t a;
    asm("{ .reg .u64 t; cvta.to.shared.u64 t, %1; cvt.u32.u64 %0, t; }"
        : "=r"(a) : "l"(p));
    return a;
}
__device__ __forceinline__ void mma16816(float* c, const uint32_t* a, const uint32_t* b) {
    asm volatile("mma.sync.aligned.m16n8k16.row.col.f32.bf16.bf16.f32 "
                 "{%0,%1,%2,%3}, {%4,%5,%6,%7}, {%8,%9}, {%0,%1,%2,%3};"
                 : "+f"(c[0]), "+f"(c[1]), "+f"(c[2]), "+f"(c[3])
                 : "r"(a[0]), "r"(a[1]), "r"(a[2]), "r"(a[3]),
                   "r"(b[0]), "r"(b[1]));
}
__device__ __forceinline__ void ldsm4(uint32_t* r, uint32_t addr) {
    asm volatile("ldmatrix.sync.aligned.m8n8.x4.shared.b16 {%0,%1,%2,%3}, [%4];"
                 : "=r"(r[0]), "=r"(r[1]), "=r"(r[2]), "=r"(r[3]) : "r"(addr));
}
__device__ __forceinline__ void ldsm2(uint32_t* r, uint32_t addr) {
    asm volatile("ldmatrix.sync.aligned.m8n8.x2.shared.b16 {%0,%1}, [%2];"
                 : "=r"(r[0]), "=r"(r[1]) : "r"(addr));
}
__device__ __forceinline__ void cp16(uint32_t dst, const void* src) {
    size_t g;
    asm("cvta.to.global.u64 %0, %1;" : "=l"(g) : "l"(src));
    asm volatile("cp.async.ca.shared.global [%0], [%1], 16;"
                 :: "r"(dst), "l"(g) : "memory");
}

// fp32 -> bf16 hi/lo split
__device__ __forceinline__ void split2(float v0, float v1, uint32_t& h, uint32_t& l) {
    asm("cvt.rn.bf16x2.f32 %0, %1, %2;" : "=r"(h) : "f"(v1), "f"(v0));
    float h0 = __uint_as_float(h << 16);
    float h1 = __uint_as_float(h & 0xffff0000u);
    float l0 = v0 - h0, l1 = v1 - h1;
    asm("cvt.rn.bf16x2.f32 %0, %1, %2;" : "=r"(l) : "f"(l1), "f"(l0));
}
__device__ __forceinline__ void split8(const float* v, uint4& hi, uint4& lo) {
    uint32_t hs[4], ls[4];
    #pragma unroll
    for (int p = 0; p < 4; p++) split2(v[2 * p], v[2 * p + 1], hs[p], ls[p]);
    hi = make_uint4(hs[0], hs[1], hs[2], hs[3]);
    lo = make_uint4(ls[0], ls[1], ls[2], ls[3]);
}

// ---------------------------------------------------------------------------
// K1: inv = exp(-lgs); muinv = mu*inv; init accumulators/rowmax
// ---------------------------------------------------------------------------
__global__ void inv_kernel(const float* __restrict__ mu,
                           const float* __restrict__ lgs) {
    int i = blockIdx.x * 256 + threadIdx.x;
    if (i < NG * HD) {
        float v = expf(-lgs[i]);
        g_inv[i]   = v;
        g_muinv[i] = mu[i] * v;
    }
    if (blockIdx.x == 0 && threadIdx.x < 32) {
        if (threadIdx.x < NG)  { g_cnt[threadIdx.x] = 0.f; g_sum[threadIdx.x] = 0.f; }
        if (threadIdx.x < BSZ) g_rowmax_u[threadIdx.x] = 0u;
    }
}

// ---------------------------------------------------------------------------
// K2: W2 = [q rows(16); q*inv_g rows(80); muinv rows(5); zeros] split hi/lo
// ---------------------------------------------------------------------------
__global__ void w2_kernel(const float* __restrict__ q) {
    int i = blockIdx.x * 256 + threadIdx.x;
    if (i >= 128 * HD) return;
    int m = i / HD, h = i - m * HD;
    float w = 0.f;
    if (m < BSZ) w = q[m * HD + h];
    else if (m < NM) {
        int bg = m - BSZ;
        int b = bg / NG, g = bg - b * NG;
        w = q[b * HD + h] * g_inv[g * HD + h];
    } else if (m < NM + NG) {
        w = g_muinv[(m - NM) * HD + h];
    }
    __nv_bfloat16 hb = __float2bfloat16(w);
    float lo = w - __bfloat162float(hb);
    g_W2h[i] = hb;
    g_W2l[i] = __float2bfloat16(lo);
}

// ---------------------------------------------------------------------------
// K3: per-(b,g) constants Cbg
// ---------------------------------------------------------------------------
__global__ void cbg_kernel(const float* __restrict__ q,
                           const float* __restrict__ mu,
                           const float* __restrict__ lgs,
                           const float* __restrict__ pi) {
    int job = blockIdx.x * 8 + (threadIdx.x >> 5);
    int lane = threadIdx.x & 31;
    if (job >= BSZ * NG) return;
    int b = job / NG, g = job - b * NG;

    float a1 = 0.f, a2 = 0.f;
    for (int h = lane; h < HD; h += 32) {
        float iv = g_inv[g * HD + h];
        float mv = g_muinv[g * HD + h];
        float qv = q[b * HD + h];
        float m_ = mu[g * HD + h];
        a1 += lgs[g * HD + h] + qv * qv * iv + m_ * mv;
        a2 += qv * mv;
    }
    a1 = wred(a1); a2 = wred(a2);
    if (lane == 0) {
        float m = pi[0];
        #pragma unroll
        for (int i = 1; i < NG; i++) m = fmaxf(m, pi[i]);
        float s = 0.f;
        #pragma unroll
        for (int i = 0; i < NG; i++) s += expf(pi[i] - m);
        float lse = m + logf(s);
        const float LG2PID = 768.0f * 1.8378770351409912f;
        g_Cbg[job] = (pi[g] - lse) - 0.5f * (LG2PID + a1) + a2;
    }
}

// ===========================================================================
// K4: HMMA bf16x3 fused GEMM (mma.sync.m16n8k16)
//   S[0:96]   = W @ feat^T            (rows 96-100 give Sam)
//   D2[g][n]  = inv @ (feat^2)^T      (Saa)
//   129 blocks x 64 cols; 128 threads = 4 warps (2M x 2N); 48 k16 stages.
// ===========================================================================
#define NSTG  48
#define AS_HI 0
#define AS_LO 6144
#define BS_HI 12288
#define BS_LO 15360
#define SQ_HI 18432
#define SQ_LO 21504
#define IV_HI 24576
#define IV_LO 32336
#define ZROW  40096
#define SMTOT 40112

__global__ __launch_bounds__(128) void gemm_mma_kernel(const float* __restrict__ sk,
                                                       const float* __restrict__ qu) {
    __shared__ __align__(1024) unsigned char smem[SMTOT];
    const uint32_t sb = smem_u32(smem);
    const int tid = threadIdx.x;
    const int lane = tid & 31;
    const int warp = tid >> 5;
    const int mi = warp >> 1;       // 0,1 : rows mi*64..+63
    const int ni = warp & 1;        // 0,1 : cols ni*32..+31
    const int n0 = blockIdx.x * 64;

    // ---- one-time: inv hi/lo into smem (5 rows x 768, stride 1552B) + zero row
    for (int i = tid; i < 5 * 384; i += 128) {
        int r = i / 384, kp = i - r * 384;
        float2 v = *(const float2*)(g_inv + r * HD + kp * 2);
        uint32_t h, l;
        split2(v.x, v.y, h, l);
        *(uint32_t*)(smem + IV_HI + r * 1552 + kp * 4) = h;
        *(uint32_t*)(smem + IV_LO + r * 1552 + kp * 4) = l;
    }
    if (tid < 4) *(uint32_t*)(smem + ZROW + tid * 4) = 0u;

    // ---- loader mappings
    const int col = tid >> 1;                 // 0..63
    const int kq  = (tid & 1) * 8;            // 0 or 8
    const int n   = n0 + col;
    const bool okB = (n < NTOT);
    const float* bsrc = okB ? ((n < BSZ) ? sk + n * HD : qu + (size_t)(n - BSZ) * HD)
                            : sk;
    const __nv_bfloat16* wh = g_W2h + tid * HD;   // row tid
    const __nv_bfloat16* wl = g_W2l + tid * HD;
    const uint32_t aDstH = sb + AS_HI + tid * 48;
    const uint32_t aDstL = sb + AS_LO + tid * 48;
    const uint32_t bDst  = sb + BS_HI + col * 48 + kq * 2;

    // ---- fragment base addresses
    const uint32_t aBase = sb + AS_HI + (mi * 64 + (lane & 15)) * 48 + (lane >> 4) * 16;
    const uint32_t bBase = sb + BS_HI + (ni * 32 + (lane & 7)) * 48 + ((lane >> 3) & 1) * 16;
    const int rr = lane & 15;
    uint32_t ivbH, ivbL; int ivstep;
    if (rr < 5) {
        ivbH = sb + IV_HI + rr * 1552 + (lane >> 4) * 16;
        ivbL = sb + IV_LO + rr * 1552 + (lane >> 4) * 16;
        ivstep = 32;
    } else {
        ivbH = sb + ZROW; ivbL = sb + ZROW; ivstep = 0;
    }

    float acc[4][4][4];
    #pragma unroll
    for (int a = 0; a < 4; a++)
        #pragma unroll
        for (int b = 0; b < 4; b++)
            #pragma unroll
            for (int c = 0; c < 4; c++) acc[a][b][c] = 0.f;
    float d2[2][4] = {{0.f, 0.f, 0.f, 0.f}, {0.f, 0.f, 0.f, 0.f}};

    // B prefetch (distance 2)
    float4 pb[2][2];
    const float4 z4 = make_float4(0.f, 0.f, 0.f, 0.f);
    pb[0][0] = okB ? *(const float4*)(bsrc + kq)      : z4;
    pb[0][1] = okB ? *(const float4*)(bsrc + kq + 4)  : z4;
    pb[1][0] = okB ? *(const float4*)(bsrc + 16 + kq) : z4;
    pb[1][1] = okB ? *(const float4*)(bsrc + 16 + kq + 4) : z4;

    for (int s = 0; s < NSTG; s++) {
        __syncthreads();
        // A: cp.async this stage's 32B per row (hi+lo)
        cp16(aDstH,      wh + s * 16);
        cp16(aDstH + 16, wh + s * 16 + 8);
        cp16(aDstL,      wl + s * 16);
        cp16(aDstL + 16, wl + s * 16 + 8);
        asm volatile("cp.async.commit_group;" ::: "memory");

        // B: convert + store current stage
        const int bf = s & 1;
        float v[8];
        v[0] = pb[bf][0].x; v[1] = pb[bf][0].y; v[2] = pb[bf][0].z; v[3] = pb[bf][0].w;
        v[4] = pb[bf][1].x; v[5] = pb[bf][1].y; v[6] = pb[bf][1].z; v[7] = pb[bf][1].w;
        uint4 hi, lo;
        split8(v, hi, lo);
        *(uint4*)(smem + BS_HI + col * 48 + kq * 2) = hi;
        *(uint4*)(smem + BS_LO + col * 48 + kq * 2) = lo;
        #pragma unroll
        for (int i = 0; i < 8; i++) v[i] = v[i] * v[i];
        split8(v, hi, lo);
        *(uint4*)(smem + SQ_HI + col * 48 + kq * 2) = hi;
        *(uint4*)(smem + SQ_LO + col * 48 + kq * 2) = lo;

        // prefetch B for stage s+2
        if (s + 2 < NSTG) {
            pb[bf][0] = okB ? *(const float4*)(bsrc + (s + 2) * 16 + kq)     : z4;
            pb[bf][1] = okB ? *(const float4*)(bsrc + (s + 2) * 16 + kq + 4) : z4;
        }
        asm volatile("cp.async.wait_group 0;" ::: "memory");
        __syncthreads();

        // fragments
        uint32_t ah[4][4], al[4][4];
        #pragma unroll
        for (int mt = 0; mt < 4; mt++) {
            ldsm4(ah[mt], aBase + mt * (16 * 48));
            ldsm4(al[mt], aBase + mt * (16 * 48) + (AS_LO - AS_HI));
        }
        uint32_t bh[4][2], bl[4][2];
        #pragma unroll
        for (int nt = 0; nt < 4; nt++) {
            ldsm2(bh[nt], bBase + nt * (8 * 48));
            ldsm2(bl[nt], bBase + nt * (8 * 48) + (BS_LO - BS_HI));
        }
        uint32_t sqh[2][2], sql[2][2];
        #pragma unroll
        for (int jj = 0; jj < 2; jj++) {
            int nt = 2 * jj + mi;
            ldsm2(sqh[jj], bBase + nt * (8 * 48) + (SQ_HI - BS_HI));
            ldsm2(sql[jj], bBase + nt * (8 * 48) + (SQ_LO - BS_HI));
        }
        uint32_t ivh[4], ivl[4];
        ldsm4(ivh, ivbH + s * ivstep);
        ldsm4(ivl, ivbL + s * ivstep);

        // main mma: 3 passes
        #pragma unroll
        for (int mt = 0; mt < 4; mt++)
            #pragma unroll
            for (int nt = 0; nt < 4; nt++) {
                mma16816(acc[mt][nt], ah[mt], bh[nt]);
                mma16816(acc[mt][nt], ah[mt], bl[nt]);
                mma16816(acc[mt][nt], al[mt], bh[nt]);
            }
        // Saa mma
        #pragma unroll
        for (int jj = 0; jj < 2; jj++) {
            mma16816(d2[jj], ivh, sqh[jj]);
            mma16816(d2[jj], ivh, sql[jj]);
            mma16816(d2[jj], ivl, sqh[jj]);
        }
    }

    // ---- epilogue ----
    const int r0  = lane >> 2;              // 0..7
    const int c0l = (lane & 3) * 2;
    float mx0 = -3.4e38f, mx1 = -3.4e38f;

    #pragma unroll
    for (int mt = 0; mt < 4; mt++) {
        const int mbase = mi * 64 + mt * 16;
        #pragma unroll
        for (int nt = 0; nt < 4; nt++) {
            const int tb = n0 + ni * 32 + nt * 8;
            if (tb >= NTOT) continue;
            const int cg = tb + c0l;
            const int m0 = mbase + r0;
            const int m1 = m0 + 8;
            if (m0 < NM) {
                *(float2*)&g_S[(size_t)m0 * NTOT + cg] =
                    make_float2(acc[mt][nt][0], acc[mt][nt][1]);
                if (m0 < BSZ) mx0 = fmaxf(mx0, fmaxf(acc[mt][nt][0], acc[mt][nt][1]));
            } else if (m0 < NM + NG) {
                g_SaaSam[cg * 10 + 5 + (m0 - NM)]       = acc[mt][nt][0];
                g_SaaSam[(cg + 1) * 10 + 5 + (m0 - NM)] = acc[mt][nt][1];
            }
            if (m1 < NM) {
                *(float2*)&g_S[(size_t)m1 * NTOT + cg] =
                    make_float2(acc[mt][nt][2], acc[mt][nt][3]);
                if (m1 < BSZ) mx1 = fmaxf(mx1, fmaxf(acc[mt][nt][2], acc[mt][nt][3]));
            } else if (m1 < NM + NG) {
                g_SaaSam[cg * 10 + 5 + (m1 - NM)]       = acc[mt][nt][2];
                g_SaaSam[(cg + 1) * 10 + 5 + (m1 - NM)] = acc[mt][nt][3];
            }
        }
    }
    if (mi == 0) {
        // rows 0-15 live in mt=0 of the mi=0 warps
        if (r0 < BSZ)      atomicMax(&g_rowmax_u[r0], fenc(mx0));
        if (r0 + 8 < BSZ)  atomicMax(&g_rowmax_u[r0 + 8], fenc(mx1));
    }
    // Saa (D2) epilogue: rows g = r0 < 5
    #pragma unroll
    for (int jj = 0; jj < 2; jj++) {
        const int nt = 2 * jj + mi;
        const int tb = n0 + ni * 32 + nt * 8;
        if (tb < NTOT && r0 < NG) {
            const int cg = tb + c0l;
            g_SaaSam[cg * 10 + r0]       = d2[jj][0];
            g_SaaSam[(cg + 1) * 10 + r0] = d2[jj][1];
        }
    }
}

// ---------------------------------------------------------------------------
// K5: fused epilogue over all (b, n) cells
// ---------------------------------------------------------------------------
__global__ __launch_bounds__(256) void epi_kernel(const float* __restrict__ rank_mean,
                                                  float* __restrict__ out) {
    __shared__ float s_cnt[NG], s_sum[NG];
    const int tid = threadIdx.x;
    if (tid < NG) { s_cnt[tid] = 0.f; s_sum[tid] = 0.f; }
    __syncthreads();

    const int idx = blockIdx.x * 256 + tid;
    const int b = idx / NTOT;
    const int n = idx - b * NTOT;

    const float sim = g_S[b * NTOT + n];

    float lg[NG], ev[NG];
    #pragma unroll
    for (int g = 0; g < NG; g++) {
        float Sqa = g_S[(size_t)(BSZ + b * NG + g) * NTOT + n];
        float Saa = g_SaaSam[n * 10 + g];
        float Sam = g_SaaSam[n * 10 + 5 + g];
        lg[g] = g_Cbg[b * NG + g] + Sqa - 0.5f * Saa - Sam;
    }
    float m = lg[0]; int bi = 0;
    #pragma unroll
    for (int g = 1; g < NG; g++) if (lg[g] > m) { m = lg[g]; bi = g; }

    float sum = 0.f;
    #pragma unroll
    for (int g = 0; g < NG; g++) {
        float ln = lg[g] - m;
        out[OFF_GLOG + (size_t)idx * NG + g] = ln;
        float e = __expf(ln);
        ev[g] = e; sum += e;
    }
    float isum = 1.f / sum;
    #pragma unroll
    for (int g = 0; g < NG; g++)
        out[OFF_GPRB + (size_t)idx * NG + g] = ev[g] * isum;

    float bd = fabsf(sim - rank_mean[0]); int cp = 0;
    #pragma unroll
    for (int g = 1; g < NG; g++) {
        float d = fabsf(sim - rank_mean[g]);
        if (d < bd) { bd = d; cp = g; }
    }
    int cd = (int)floorf((sim + 1.0f) / 2.0f * 5.0f);

    bool golden = (n < BSZ) && (n == ((b + 8) & 15));
    bool eye    = (n == b);

    out[OFF_CLOG + idx] = sim - fdec(g_rowmax_u[b]);
    out[OFF_ACC  + idx] = eye ? 0.f : sim;
    out[OFF_GLBL + idx] = (float)((eye || golden) ? (NG - 1) : cp);
    out[OFF_CLBL + idx] = (float)(golden ? (NG - 1) : bi);
    out[OFF_CDST + idx] = (float)cd;

    atomicAdd(&s_cnt[bi], 1.f);
    atomicAdd(&s_sum[bi], sim);
    __syncthreads();
    if (tid < NG) {
        atomicAdd(&g_cnt[tid], s_cnt[tid]);
        atomicAdd(&g_sum[tid], s_sum[tid]);
    }
}

// ---------------------------------------------------------------------------
// K6: rank-mean EMA finalize
// ---------------------------------------------------------------------------
__global__ void finish_kernel(const float* __restrict__ rank_mean,
                              float* __restrict__ out) {
    int g = threadIdx.x;
    if (g < NG) {
        float c = g_cnt[g], s = g_sum[g];
        float cur = s / (c + 1e-12f);
        float upd = (c != 0.f) ? 1.f : 0.f;
        out[OFF_NRM + g] = (1.f - upd * 0.1f) * rank_mean[g] + upd * 0.1f * cur;
    }
}

// ---------------------------------------------------------------------------
extern "C" void kernel_launch(void* const* d_in, const int* in_sizes, int n_in,
                              void* d_out, int out_size) {
    const float* sent_q    = (const float*)d_in[0];
    const float* sent_k    = (const float*)d_in[1];
    const float* queue     = (const float*)d_in[2];
    const float* mu        = (const float*)d_in[3];
    const float* lg_sigma2 = (const float*)d_in[4];
    const float* pi        = (const float*)d_in[5];
    const float* rank_mean = (const float*)d_in[6];
    float* out = (float*)d_out;

    inv_kernel<<<(NG * HD + 255) / 256, 256>>>(mu, lg_sigma2);
    w2_kernel<<<(128 * HD + 255) / 256, 256>>>(sent_q);
    cbg_kernel<<<10, 256>>>(sent_q, mu, lg_sigma2, pi);
    gemm_mma_kernel<<<(NTOT + 63) / 64, 128>>>(sent_k, queue);
    epi_kernel<<<(BSZ * NTOT) / 256, 256>>>(rank_mean, out);
    finish_kernel<<<1, 32>>>(rank_mean, out);
}

// round 6
// speedup vs baseline: 1.9779x; 1.1740x over previous
#include <cuda_runtime.h>
#include <cuda_bf16.h>
#include <math.h>
#include <stdint.h>

#define BSZ   16
#define NTOT  8208
#define HD    768
#define NG    5
#define NM    96

// output offsets (flattened concat of the 8 reference outputs, float32)
#define OFF_GLOG 0
#define OFF_GPRB 656640
#define OFF_CLOG 1313280
#define OFF_ACC  1444608
#define OFF_NRM  1575936
#define OFF_GLBL 1575941
#define OFF_CLBL 1707269
#define OFF_CDST 1838597

__device__ float g_inv[NG * HD];
__device__ float g_muinv[NG * HD];
__device__ __nv_bfloat16 g_W2h[128 * HD];
__device__ __nv_bfloat16 g_W2l[128 * HD];
__device__ float g_Cbg[BSZ * NG];
__device__ float g_SaaSam[NTOT * 10];
__device__ float g_S[NM * NTOT];
__device__ unsigned g_rowmax_u[BSZ];
__device__ float g_cnt[NG];
__device__ float g_sum[NG];

__device__ __forceinline__ float wred(float v) {
    #pragma unroll
    for (int o = 16; o; o >>= 1) v += __shfl_down_sync(0xffffffffu, v, o);
    return v;
}
__device__ __forceinline__ unsigned fenc(float f) {
    unsigned b = __float_as_uint(f);
    return (b & 0x80000000u) ? ~b : (b | 0x80000000u);
}
__device__ __forceinline__ float fdec(unsigned u) {
    return (u & 0x80000000u) ? __uint_as_float(u ^ 0x80000000u)
                             : __uint_as_float(~u);
}

// ---------------------------------------------------------------------------
// mma.sync / ldmatrix / cp.async helpers (plain sm_80+)
// ---------------------------------------------------------------------------
__device__ __forceinline__ uint32_t smem_u32(const void* p) {
    uint32_t a;
    asm("{ .reg .u64 t; cvta.to.shared.u64 t, %1; cvt.u32.u64 %0, t; }"
        : "=r"(a) : "l"(p));
    return a;
}
__device__ __forceinline__ void mma16816(float* c, const uint32_t* a, const uint32_t* b) {
    asm volatile("mma.sync.aligned.m16n8k16.row.col.f32.bf16.bf16.f32 "
                 "{%0,%1,%2,%3}, {%4,%5,%6,%7}, {%8,%9}, {%0,%1,%2,%3};"
                 : "+f"(c[0]), "+f"(c[1]), "+f"(c[2]), "+f"(c[3])
                 : "r"(a[0]), "r"(a[1]), "r"(a[2]), "r"(a[3]),
                   "r"(b[0]), "r"(b[1]));
}
__device__ __forceinline__ void ldsm4(uint32_t* r, uint32_t addr) {
    asm volatile("ldmatrix.sync.aligned.m8n8.x4.shared.b16 {%0,%1,%2,%3}, [%4];"
                 : "=r"(r[0]), "=r"(r[1]), "=r"(r[2]), "=r"(r[3]) : "r"(addr));
}
__device__ __forceinline__ void ldsm2(uint32_t* r, uint32_t addr) {
    asm volatile("ldmatrix.sync.aligned.m8n8.x2.shared.b16 {%0,%1}, [%2];"
                 : "=r"(r[0]), "=r"(r[1]) : "r"(addr));
}
__device__ __forceinline__ void cp16(uint32_t dst, const void* src) {
    size_t g;
    asm("cvta.to.global.u64 %0, %1;" : "=l"(g) : "l"(src));
    asm volatile("cp.async.ca.shared.global [%0], [%1], 16;"
                 :: "r"(dst), "l"(g) : "memory");
}

__device__ __forceinline__ void split2(float v0, float v1, uint32_t& h, uint32_t& l) {
    asm("cvt.rn.bf16x2.f32 %0, %1, %2;" : "=r"(h) : "f"(v1), "f"(v0));
    float h0 = __uint_as_float(h << 16);
    float h1 = __uint_as_float(h & 0xffff0000u);
    float l0 = v0 - h0, l1 = v1 - h1;
    asm("cvt.rn.bf16x2.f32 %0, %1, %2;" : "=r"(l) : "f"(l1), "f"(l0));
}
__device__ __forceinline__ void split8(const float* v, uint4& hi, uint4& lo) {
    uint32_t hs[4], ls[4];
    #pragma unroll
    for (int p = 0; p < 4; p++) split2(v[2 * p], v[2 * p + 1], hs[p], ls[p]);
    hi = make_uint4(hs[0], hs[1], hs[2], hs[3]);
    lo = make_uint4(ls[0], ls[1], ls[2], ls[3]);
}

// ---------------------------------------------------------------------------
// K1: inv = exp(-lgs); muinv = mu*inv; init accumulators/rowmax
// ---------------------------------------------------------------------------
__global__ void inv_kernel(const float* __restrict__ mu,
                           const float* __restrict__ lgs) {
    int i = blockIdx.x * 256 + threadIdx.x;
    if (i < NG * HD) {
        float v = expf(-lgs[i]);
        g_inv[i]   = v;
        g_muinv[i] = mu[i] * v;
    }
    if (blockIdx.x == 0 && threadIdx.x < 32) {
        if (threadIdx.x < NG)  { g_cnt[threadIdx.x] = 0.f; g_sum[threadIdx.x] = 0.f; }
        if (threadIdx.x < BSZ) g_rowmax_u[threadIdx.x] = 0u;
    }
}

// ---------------------------------------------------------------------------
// K2: W2 = [q rows(16); q*inv_g rows(80); muinv rows(5); zeros] split hi/lo
// ---------------------------------------------------------------------------
__global__ void w2_kernel(const float* __restrict__ q) {
    int i = blockIdx.x * 256 + threadIdx.x;
    if (i >= 128 * HD) return;
    int m = i / HD, h = i - m * HD;
    float w = 0.f;
    if (m < BSZ) w = q[m * HD + h];
    else if (m < NM) {
        int bg = m - BSZ;
        int b = bg / NG, g = bg - b * NG;
        w = q[b * HD + h] * g_inv[g * HD + h];
    } else if (m < NM + NG) {
        w = g_muinv[(m - NM) * HD + h];
    }
    __nv_bfloat16 hb = __float2bfloat16(w);
    float lo = w - __bfloat162float(hb);
    g_W2h[i] = hb;
    g_W2l[i] = __float2bfloat16(lo);
}

// ---------------------------------------------------------------------------
// K3: per-(b,g) constants Cbg
// ---------------------------------------------------------------------------
__global__ void cbg_kernel(const float* __restrict__ q,
                           const float* __restrict__ mu,
                           const float* __restrict__ lgs,
                           const float* __restrict__ pi) {
    int job = blockIdx.x * 8 + (threadIdx.x >> 5);
    int lane = threadIdx.x & 31;
    if (job >= BSZ * NG) return;
    int b = job / NG, g = job - b * NG;

    float a1 = 0.f, a2 = 0.f;
    for (int h = lane; h < HD; h += 32) {
        float iv = g_inv[g * HD + h];
        float mv = g_muinv[g * HD + h];
        float qv = q[b * HD + h];
        float m_ = mu[g * HD + h];
        a1 += lgs[g * HD + h] + qv * qv * iv + m_ * mv;
        a2 += qv * mv;
    }
    a1 = wred(a1); a2 = wred(a2);
    if (lane == 0) {
        float m = pi[0];
        #pragma unroll
        for (int i = 1; i < NG; i++) m = fmaxf(m, pi[i]);
        float s = 0.f;
        #pragma unroll
        for (int i = 0; i < NG; i++) s += expf(pi[i] - m);
        float lse = m + logf(s);
        const float LG2PID = 768.0f * 1.8378770351409912f;
        g_Cbg[job] = (pi[g] - lse) - 0.5f * (LG2PID + a1) + a2;
    }
}

// ===========================================================================
// K4: HMMA bf16x3 fused GEMM, 256 threads (8 warps = 4M x 2N), k32 stages,
//     double-buffered A (cp.async) and B (reg prefetch + convert).
// ===========================================================================
#define NSTG  24
#define A_HI  0
#define A_LO  20480
#define B_HI  40960
#define B_LO  51200
#define SQ_HI 61440
#define SQ_LO 71680
#define IV_HI 81920
#define IV_LO 89680
#define ZROW  97440
#define SMTOT 97456

__global__ __launch_bounds__(256, 1) void gemm_mma_kernel(const float* __restrict__ sk,
                                                          const float* __restrict__ qu) {
    extern __shared__ __align__(1024) unsigned char smem[];
    const uint32_t sb = smem_u32(smem);
    const int tid = threadIdx.x;
    const int lane = tid & 31;
    const int warp = tid >> 5;
    const int mi = warp >> 1;       // 0..3 : rows mi*32..+31
    const int ni = warp & 1;        // 0..1 : cols ni*32..+31
    const int n0 = blockIdx.x * 64;

    // ---- one-time: inv hi/lo into smem + zero row
    for (int i = tid; i < 5 * 384; i += 256) {
        int r = i / 384, kp = i - r * 384;
        float2 v = *(const float2*)(g_inv + r * HD + kp * 2);
        uint32_t h, l;
        split2(v.x, v.y, h, l);
        *(uint32_t*)(smem + IV_HI + r * 1552 + kp * 4) = h;
        *(uint32_t*)(smem + IV_LO + r * 1552 + kp * 4) = l;
    }
    if (tid < 4) *(uint32_t*)(smem + ZROW + tid * 4) = 0u;

    // ---- loader mappings
    const int arow = tid >> 1, apart = tid & 1;
    const __nv_bfloat16* asrc = (apart ? g_W2l : g_W2h) + arow * HD;
    const uint32_t aDst = sb + A_HI + apart * 20480 + arow * 80;

    const int col = tid >> 2;                 // 0..63
    const int kq  = (tid & 3) * 8;            // 0,8,16,24
    const int n   = n0 + col;
    const bool okB = (n < NTOT);
    const float* bsrc = okB ? ((n < BSZ) ? sk + n * HD : qu + (size_t)(n - BSZ) * HD)
                            : sk;
    const uint32_t bOffT = col * 80 + kq * 2;  // byte offset within B buffer

    // ---- fragment base addresses
    const uint32_t aB = sb + A_HI + (mi * 32 + (lane & 15)) * 80 + (lane >> 4) * 16;
    const uint32_t bB = sb + B_HI + (ni * 32 + (lane & 7)) * 80 + ((lane >> 3) & 1) * 16;
    const int rr = lane & 15;
    const uint32_t ivH = (rr < 5) ? sb + IV_HI + rr * 1552 + (lane >> 4) * 16 : sb + ZROW;
    const uint32_t ivL = (rr < 5) ? sb + IV_LO + rr * 1552 + (lane >> 4) * 16 : sb + ZROW;
    const int ivs = (rr < 5) ? 32 : 0;

    float acc[2][4][4];
    #pragma unroll
    for (int a = 0; a < 2; a++)
        #pragma unroll
        for (int b = 0; b < 4; b++)
            #pragma unroll
            for (int c = 0; c < 4; c++) acc[a][b][c] = 0.f;
    float d2[2][4] = {{0.f, 0.f, 0.f, 0.f}, {0.f, 0.f, 0.f, 0.f}};

    const float4 z4 = make_float4(0.f, 0.f, 0.f, 0.f);

    // ---- prologue: stage 0 B (sync load + convert), A(0) cp.async, prefetch B(1)
    {
        float4 b0 = okB ? *(const float4*)(bsrc + kq)     : z4;
        float4 b1 = okB ? *(const float4*)(bsrc + kq + 4) : z4;
        float v[8] = {b0.x, b0.y, b0.z, b0.w, b1.x, b1.y, b1.z, b1.w};
        uint4 hi, lo;
        split8(v, hi, lo);
        *(uint4*)(smem + B_HI + bOffT) = hi;
        *(uint4*)(smem + B_LO + bOffT) = lo;
        #pragma unroll
        for (int i = 0; i < 8; i++) v[i] *= v[i];
        split8(v, hi, lo);
        *(uint4*)(smem + SQ_HI + bOffT) = hi;
        *(uint4*)(smem + SQ_LO + bOffT) = lo;
    }
    #pragma unroll
    for (int j = 0; j < 4; j++) cp16(aDst + j * 16, asrc + j * 8);
    asm volatile("cp.async.commit_group;" ::: "memory");

    float4 pb0 = okB ? *(const float4*)(bsrc + 32 + kq)     : z4;
    float4 pb1 = okB ? *(const float4*)(bsrc + 32 + kq + 4) : z4;

    for (int s = 0; s < NSTG; s++) {
        const int bufn = s & 1;
        asm volatile("cp.async.wait_group 0;" ::: "memory");
        __syncthreads();

        if (s + 1 < NSTG) {
            const int nb = bufn ^ 1;
            // A(s+1)
            #pragma unroll
            for (int j = 0; j < 4; j++)
                cp16(aDst + nb * 10240 + j * 16, asrc + (s + 1) * 32 + j * 8);
            asm volatile("cp.async.commit_group;" ::: "memory");
            // B(s+1): convert prefetched regs, store
            {
                float v[8] = {pb0.x, pb0.y, pb0.z, pb0.w, pb1.x, pb1.y, pb1.z, pb1.w};
                uint4 hi, lo;
                split8(v, hi, lo);
                uint32_t off = nb * 5120 + bOffT;
                *(uint4*)(smem + B_HI + off) = hi;
                *(uint4*)(smem + B_LO + off) = lo;
                #pragma unroll
                for (int i = 0; i < 8; i++) v[i] *= v[i];
                split8(v, hi, lo);
                *(uint4*)(smem + SQ_HI + off) = hi;
                *(uint4*)(smem + SQ_LO + off) = lo;
            }
            if (s + 2 < NSTG) {
                pb0 = okB ? *(const float4*)(bsrc + (s + 2) * 32 + kq)     : z4;
                pb1 = okB ? *(const float4*)(bsrc + (s + 2) * 32 + kq + 4) : z4;
            }
        }

        const uint32_t aO = bufn * 10240u;
        const uint32_t bO = bufn * 5120u;
        #pragma unroll
        for (int su = 0; su < 2; su++) {
            uint32_t ah0[4], ah1[4], al0[4], al1[4];
            ldsm4(ah0, aB + aO + su * 32);
            ldsm4(ah1, aB + aO + 16 * 80 + su * 32);
            ldsm4(al0, aB + aO + su * 32 + 20480);
            ldsm4(al1, aB + aO + 16 * 80 + su * 32 + 20480);
            uint32_t bh[4][2], bl[4][2];
            #pragma unroll
            for (int nt = 0; nt < 4; nt++) {
                ldsm2(bh[nt], bB + bO + nt * 640 + su * 32);
                ldsm2(bl[nt], bB + bO + nt * 640 + su * 32 + 10240);
            }
            #pragma unroll
            for (int nt = 0; nt < 4; nt++) {
                mma16816(acc[0][nt], ah0, bh[nt]);
                mma16816(acc[1][nt], ah1, bh[nt]);
                mma16816(acc[0][nt], ah0, bl[nt]);
                mma16816(acc[1][nt], ah1, bl[nt]);
                mma16816(acc[0][nt], al0, bh[nt]);
                mma16816(acc[1][nt], al1, bh[nt]);
            }
            if (mi < 2) {
                const int t16 = 2 * s + su;
                uint32_t ivh[4], ivl[4];
                ldsm4(ivh, ivH + t16 * ivs);
                ldsm4(ivl, ivL + t16 * ivs);
                #pragma unroll
                for (int j = 0; j < 2; j++) {
                    const int nt = mi * 2 + j;
                    uint32_t sh[2], sl[2];
                    ldsm2(sh, bB + bO + nt * 640 + su * 32 + 20480);
                    ldsm2(sl, bB + bO + nt * 640 + su * 32 + 30720);
                    mma16816(d2[j], ivh, sh);
                    mma16816(d2[j], ivh, sl);
                    mma16816(d2[j], ivl, sh);
                }
            }
        }
    }

    // ---- epilogue ----
    const int r0  = lane >> 2;
    const int c0l = (lane & 3) * 2;
    float mx0 = -3.4e38f, mx1 = -3.4e38f;

    #pragma unroll
    for (int mt = 0; mt < 2; mt++) {
        const int mb = mi * 32 + mt * 16;
        #pragma unroll
        for (int nt = 0; nt < 4; nt++) {
            const int cg = n0 + ni * 32 + nt * 8 + c0l;
            if (cg >= NTOT) continue;
            const float* c = acc[mt][nt];
            const int m0 = mb + r0, m1 = m0 + 8;
            if (m0 < NM) {
                *(float2*)&g_S[(size_t)m0 * NTOT + cg] = make_float2(c[0], c[1]);
                if (m0 < BSZ) mx0 = fmaxf(mx0, fmaxf(c[0], c[1]));
            } else if (m0 < NM + NG) {
                g_SaaSam[cg * 10 + 5 + (m0 - NM)]       = c[0];
                g_SaaSam[(cg + 1) * 10 + 5 + (m0 - NM)] = c[1];
            }
            if (m1 < NM) {
                *(float2*)&g_S[(size_t)m1 * NTOT + cg] = make_float2(c[2], c[3]);
                if (m1 < BSZ) mx1 = fmaxf(mx1, fmaxf(c[2], c[3]));
            } else if (m1 < NM + NG) {
                g_SaaSam[cg * 10 + 5 + (m1 - NM)]       = c[2];
                g_SaaSam[(cg + 1) * 10 + 5 + (m1 - NM)] = c[3];
            }
        }
    }
    if (mi == 0) {
        if (r0 < BSZ)     atomicMax(&g_rowmax_u[r0], fenc(mx0));
        if (r0 + 8 < BSZ) atomicMax(&g_rowmax_u[r0 + 8], fenc(mx1));
    }
    if (mi < 2 && r0 < NG) {
        #pragma unroll
        for (int j = 0; j < 2; j++) {
            const int nt = mi * 2 + j;
            const int cg = n0 + ni * 32 + nt * 8 + c0l;
            if (cg < NTOT) {
                g_SaaSam[cg * 10 + r0]       = d2[j][0];
                g_SaaSam[(cg + 1) * 10 + r0] = d2[j][1];
            }
        }
    }
}

// ---------------------------------------------------------------------------
// K5: fused epilogue over all (b, n) cells
// ---------------------------------------------------------------------------
__global__ __launch_bounds__(256) void epi_kernel(const float* __restrict__ rank_mean,
                                                  float* __restrict__ out) {
    __shared__ float s_cnt[NG], s_sum[NG];
    const int tid = threadIdx.x;
    if (tid < NG) { s_cnt[tid] = 0.f; s_sum[tid] = 0.f; }
    __syncthreads();

    const int idx = blockIdx.x * 256 + tid;
    const int b = idx / NTOT;
    const int n = idx - b * NTOT;

    const float sim = g_S[b * NTOT + n];

    float lg[NG], ev[NG];
    #pragma unroll
    for (int g = 0; g < NG; g++) {
        float Sqa = g_S[(size_t)(BSZ + b * NG + g) * NTOT + n];
        float Saa = g_SaaSam[n * 10 + g];
        float Sam = g_SaaSam[n * 10 + 5 + g];
        lg[g] = g_Cbg[b * NG + g] + Sqa - 0.5f * Saa - Sam;
    }
    float m = lg[0]; int bi = 0;
    #pragma unroll
    for (int g = 1; g < NG; g++) if (lg[g] > m) { m = lg[g]; bi = g; }

    float sum = 0.f;
    #pragma unroll
    for (int g = 0; g < NG; g++) {
        float ln = lg[g] - m;
        out[OFF_GLOG + (size_t)idx * NG + g] = ln;
        float e = __expf(ln);
        ev[g] = e; sum += e;
    }
    float isum = 1.f / sum;
    #pragma unroll
    for (int g = 0; g < NG; g++)
        out[OFF_GPRB + (size_t)idx * NG + g] = ev[g] * isum;

    float bd = fabsf(sim - rank_mean[0]); int cp = 0;
    #pragma unroll
    for (int g = 1; g < NG; g++) {
        float d = fabsf(sim - rank_mean[g]);
        if (d < bd) { bd = d; cp = g; }
    }
    int cd = (int)floorf((sim + 1.0f) / 2.0f * 5.0f);

    bool golden = (n < BSZ) && (n == ((b + 8) & 15));
    bool eye    = (n == b);

    out[OFF_CLOG + idx] = sim - fdec(g_rowmax_u[b]);
    out[OFF_ACC  + idx] = eye ? 0.f : sim;
    out[OFF_GLBL + idx] = (float)((eye || golden) ? (NG - 1) : cp);
    out[OFF_CLBL + idx] = (float)(golden ? (NG - 1) : bi);
    out[OFF_CDST + idx] = (float)cd;

    atomicAdd(&s_cnt[bi], 1.f);
    atomicAdd(&s_sum[bi], sim);
    __syncthreads();
    if (tid < NG) {
        atomicAdd(&g_cnt[tid], s_cnt[tid]);
        atomicAdd(&g_sum[tid], s_sum[tid]);
    }
}

// ---------------------------------------------------------------------------
// K6: rank-mean EMA finalize
// ---------------------------------------------------------------------------
__global__ void finish_kernel(const float* __restrict__ rank_mean,
                              float* __restrict__ out) {
    int g = threadIdx.x;
    if (g < NG) {
        float c = g_cnt[g], s = g_sum[g];
        float cur = s / (c + 1e-12f);
        float upd = (c != 0.f) ? 1.f : 0.f;
        out[OFF_NRM + g] = (1.f - upd * 0.1f) * rank_mean[g] + upd * 0.1f * cur;
    }
}

// ---------------------------------------------------------------------------
extern "C" void kernel_launch(void* const* d_in, const int* in_sizes, int n_in,
                              void* d_out, int out_size) {
    const float* sent_q    = (const float*)d_in[0];
    const float* sent_k    = (const float*)d_in[1];
    const float* queue     = (const float*)d_in[2];
    const float* mu        = (const float*)d_in[3];
    const float* lg_sigma2 = (const float*)d_in[4];
    const float* pi        = (const float*)d_in[5];
    const float* rank_mean = (const float*)d_in[6];
    float* out = (float*)d_out;

    cudaFuncSetAttribute(gemm_mma_kernel,
                         cudaFuncAttributeMaxDynamicSharedMemorySize, SMTOT);

    inv_kernel<<<(NG * HD + 255) / 256, 256>>>(mu, lg_sigma2);
    w2_kernel<<<(128 * HD + 255) / 256, 256>>>(sent_q);
    cbg_kernel<<<10, 256>>>(sent_q, mu, lg_sigma2, pi);
    gemm_mma_kernel<<<(NTOT + 63) / 64, 256, SMTOT>>>(sent_k, queue);
    epi_kernel<<<(BSZ * NTOT) / 256, 256>>>(rank_mean, out);
    finish_kernel<<<1, 32>>>(rank_mean, out);
}

// round 8
// speedup vs baseline: 2.0344x; 1.0286x over previous
#include <cuda_runtime.h>
#include <cuda_bf16.h>
#include <math.h>
#include <stdint.h>

#define BSZ   16
#define NTOT  8208
#define HD    768
#define NG    5
#define NM    96

// output offsets (flattened concat of the 8 reference outputs, float32)
#define OFF_GLOG 0
#define OFF_GPRB 656640
#define OFF_CLOG 1313280
#define OFF_ACC  1444608
#define OFF_NRM  1575936
#define OFF_GLBL 1575941
#define OFF_CLBL 1707269
#define OFF_CDST 1838597

__device__ float g_inv[NG * HD];
__device__ float g_muinv[NG * HD];
__device__ __nv_bfloat16 g_W2h[128 * HD];
__device__ __nv_bfloat16 g_W2l[128 * HD];
__device__ float g_Cbg[BSZ * NG];
__device__ float g_SaaSam[NTOT * 10];
__device__ float g_S[NM * NTOT];
__device__ unsigned g_rowmax_u[BSZ];
__device__ float g_cnt[NG];
__device__ float g_sum[NG];

__device__ __forceinline__ float wred(float v) {
    #pragma unroll
    for (int o = 16; o; o >>= 1) v += __shfl_down_sync(0xffffffffu, v, o);
    return v;
}
__device__ __forceinline__ unsigned fenc(float f) {
    unsigned b = __float_as_uint(f);
    return (b & 0x80000000u) ? ~b : (b | 0x80000000u);
}
__device__ __forceinline__ float fdec(unsigned u) {
    return (u & 0x80000000u) ? __uint_as_float(u ^ 0x80000000u)
                             : __uint_as_float(~u);
}

// ---------------------------------------------------------------------------
// mma.sync / ldmatrix / cp.async helpers (plain sm_80+)
// ---------------------------------------------------------------------------
__device__ __forceinline__ uint32_t smem_u32(const void* p) {
    uint32_t a;
    asm("{ .reg .u64 t; cvta.to.shared.u64 t, %1; cvt.u32.u64 %0, t; }"
        : "=r"(a) : "l"(p));
    return a;
}
__device__ __forceinline__ void mma16816(float* c, const uint32_t* a, const uint32_t* b) {
    asm volatile("mma.sync.aligned.m16n8k16.row.col.f32.bf16.bf16.f32 "
                 "{%0,%1,%2,%3}, {%4,%5,%6,%7}, {%8,%9}, {%0,%1,%2,%3};"
                 : "+f"(c[0]), "+f"(c[1]), "+f"(c[2]), "+f"(c[3])
                 : "r"(a[0]), "r"(a[1]), "r"(a[2]), "r"(a[3]),
                   "r"(b[0]), "r"(b[1]));
}
__device__ __forceinline__ void ldsm4(uint32_t* r, uint32_t addr) {
    asm volatile("ldmatrix.sync.aligned.m8n8.x4.shared.b16 {%0,%1,%2,%3}, [%4];"
                 : "=r"(r[0]), "=r"(r[1]), "=r"(r[2]), "=r"(r[3]) : "r"(addr));
}
__device__ __forceinline__ void ldsm2(uint32_t* r, uint32_t addr) {
    asm volatile("ldmatrix.sync.aligned.m8n8.x2.shared.b16 {%0,%1}, [%2];"
                 : "=r"(r[0]), "=r"(r[1]) : "r"(addr));
}
__device__ __forceinline__ void cp16(uint32_t dst, const void* src) {
    size_t g;
    asm("cvta.to.global.u64 %0, %1;" : "=l"(g) : "l"(src));
    asm volatile("cp.async.ca.shared.global [%0], [%1], 16;"
                 :: "r"(dst), "l"(g) : "memory");
}

__device__ __forceinline__ void split2(float v0, float v1, uint32_t& h, uint32_t& l) {
    asm("cvt.rn.bf16x2.f32 %0, %1, %2;" : "=r"(h) : "f"(v1), "f"(v0));
    float h0 = __uint_as_float(h << 16);
    float h1 = __uint_as_float(h & 0xffff0000u);
    float l0 = v0 - h0, l1 = v1 - h1;
    asm("cvt.rn.bf16x2.f32 %0, %1, %2;" : "=r"(l) : "f"(l1), "f"(l0));
}

// ---------------------------------------------------------------------------
// K1: inv = exp(-lgs); muinv = mu*inv; init accumulators/rowmax
// ---------------------------------------------------------------------------
__global__ void inv_kernel(const float* __restrict__ mu,
                           const float* __restrict__ lgs) {
    int i = blockIdx.x * 256 + threadIdx.x;
    if (i < NG * HD) {
        float v = expf(-lgs[i]);
        g_inv[i]   = v;
        g_muinv[i] = mu[i] * v;
    }
    if (blockIdx.x == 0 && threadIdx.x < 32) {
        if (threadIdx.x < NG)  { g_cnt[threadIdx.x] = 0.f; g_sum[threadIdx.x] = 0.f; }
        if (threadIdx.x < BSZ) g_rowmax_u[threadIdx.x] = 0u;
    }
}

// ---------------------------------------------------------------------------
// K2: W2 = [q rows(16); q*inv_g rows(80); muinv rows(5); zeros] split hi/lo
// ---------------------------------------------------------------------------
__global__ void w2_kernel(const float* __restrict__ q) {
    int i = blockIdx.x * 256 + threadIdx.x;
    if (i >= 128 * HD) return;
    int m = i / HD, h = i - m * HD;
    float w = 0.f;
    if (m < BSZ) w = q[m * HD + h];
    else if (m < NM) {
        int bg = m - BSZ;
        int b = bg / NG, g = bg - b * NG;
        w = q[b * HD + h] * g_inv[g * HD + h];
    } else if (m < NM + NG) {
        w = g_muinv[(m - NM) * HD + h];
    }
    __nv_bfloat16 hb = __float2bfloat16(w);
    float lo = w - __bfloat162float(hb);
    g_W2h[i] = hb;
    g_W2l[i] = __float2bfloat16(lo);
}

// ---------------------------------------------------------------------------
// K3: per-(b,g) constants Cbg
// ---------------------------------------------------------------------------
__global__ void cbg_kernel(const float* __restrict__ q,
                           const float* __restrict__ mu,
                           const float* __restrict__ lgs,
                           const float* __restrict__ pi) {
    int job = blockIdx.x * 8 + (threadIdx.x >> 5);
    int lane = threadIdx.x & 31;
    if (job >= BSZ * NG) return;
    int b = job / NG, g = job - b * NG;

    float a1 = 0.f, a2 = 0.f;
    for (int h = lane; h < HD; h += 32) {
        float iv = g_inv[g * HD + h];
        float mv = g_muinv[g * HD + h];
        float qv = q[b * HD + h];
        float m_ = mu[g * HD + h];
        a1 += lgs[g * HD + h] + qv * qv * iv + m_ * mv;
        a2 += qv * mv;
    }
    a1 = wred(a1); a2 = wred(a2);
    if (lane == 0) {
        float m = pi[0];
        #pragma unroll
        for (int i = 1; i < NG; i++) m = fmaxf(m, pi[i]);
        float s = 0.f;
        #pragma unroll
        for (int i = 0; i < NG; i++) s += expf(pi[i] - m);
        float lse = m + logf(s);
        const float LG2PID = 768.0f * 1.8378770351409912f;
        g_Cbg[job] = (pi[g] - lse) - 0.5f * (LG2PID + a1) + a2;
    }
}

// ===========================================================================
// K4: HMMA bf16x3 fused GEMM, 512 threads (16 warps = 4M x 4N), k32 stages,
//     double-buffered A (cp.async) + B (reg prefetch + convert).
// ===========================================================================
#define NSTG  24
#define A_HI  0
#define A_LO  20480
#define B_HI  40960
#define B_LO  51200
#define SQ_HI 61440
#define SQ_LO 71680
#define IV_HI 81920
#define IV_LO 89680
#define ZROW  97440
#define SMTOT 97456

__global__ __launch_bounds__(512, 1) void gemm_mma_kernel(const float* __restrict__ sk,
                                                          const float* __restrict__ qu) {
    extern __shared__ __align__(1024) unsigned char smem[];
    const uint32_t sb = smem_u32(smem);
    const int tid = threadIdx.x;
    const int lane = tid & 31;
    const int warp = tid >> 5;
    const int mi = warp >> 2;       // 0..3 : rows mi*32..+31
    const int ni = warp & 3;        // 0..3 : cols ni*16..+15
    const int n0 = blockIdx.x * 64;

    // ---- one-time: inv hi/lo into smem + zero row
    for (int i = tid; i < 5 * 384; i += 512) {
        int r = i / 384, kp = i - r * 384;
        float2 v = *(const float2*)(g_inv + r * HD + kp * 2);
        uint32_t h, l;
        split2(v.x, v.y, h, l);
        *(uint32_t*)(smem + IV_HI + r * 1552 + kp * 4) = h;
        *(uint32_t*)(smem + IV_LO + r * 1552 + kp * 4) = l;
    }
    if (tid < 4) *(uint32_t*)(smem + ZROW + tid * 4) = 0u;

    // ---- loader mappings
    // A: 128 rows x 2 parts x 2 chunk-pairs = 512 jobs (2x cp16 each)
    const int arow = tid >> 2, apart = (tid >> 1) & 1, ach = (tid & 1) * 2;
    const __nv_bfloat16* asrc = (apart ? g_W2l : g_W2h) + arow * HD + ach * 8;
    const uint32_t aDst = sb + A_HI + apart * 20480 + arow * 80 + ach * 16;

    // B: 64 cols x 8 k-quads (float4 each)
    const int col = tid >> 3;                 // 0..63
    const int kq  = (tid & 7) * 4;            // 0..28
    const int n   = n0 + col;
    const bool okB = (n < NTOT);
    const float* bsrc = okB ? ((n < BSZ) ? sk + n * HD : qu + (size_t)(n - BSZ) * HD)
                            : sk;
    const uint32_t bOffT = col * 80 + kq * 2;

    // ---- fragment base addresses
    const uint32_t aB = sb + A_HI + (mi * 32 + (lane & 15)) * 80 + (lane >> 4) * 16;
    const uint32_t bB = sb + B_HI + (ni * 16 + (lane & 7)) * 80 + ((lane >> 3) & 1) * 16;
    const int rr = lane & 15;
    const uint32_t ivH = (rr < 5) ? sb + IV_HI + rr * 1552 + (lane >> 4) * 16 : sb + ZROW;
    const uint32_t ivL = (rr < 5) ? sb + IV_LO + rr * 1552 + (lane >> 4) * 16 : sb + ZROW;
    const int ivs = (rr < 5) ? 32 : 0;
    // Saa tile for this warp (warps with mi<2): global n8-tile tt = ni*2+mi
    const int tt = ni * 2 + mi;
    const uint32_t sqB = sb + SQ_HI + (tt * 8 + (lane & 7)) * 80 + ((lane >> 3) & 1) * 16;

    float acc[2][2][4];
    #pragma unroll
    for (int a = 0; a < 2; a++)
        #pragma unroll
        for (int b = 0; b < 2; b++)
            #pragma unroll
            for (int c = 0; c < 4; c++) acc[a][b][c] = 0.f;
    float d2[4] = {0.f, 0.f, 0.f, 0.f};

    const float4 z4 = make_float4(0.f, 0.f, 0.f, 0.f);

    // ---- prologue: stage 0 B (sync load + convert), A(0) cp.async, prefetch B(1)
    {
        float4 b0 = okB ? *(const float4*)(bsrc + kq) : z4;
        uint32_t h0, l0, h1, l1;
        split2(b0.x, b0.y, h0, l0);
        split2(b0.z, b0.w, h1, l1);
        *(uint2*)(smem + B_HI + bOffT) = make_uint2(h0, h1);
        *(uint2*)(smem + B_LO + bOffT) = make_uint2(l0, l1);
        split2(b0.x * b0.x, b0.y * b0.y, h0, l0);
        split2(b0.z * b0.z, b0.w * b0.w, h1, l1);
        *(uint2*)(smem + SQ_HI + bOffT) = make_uint2(h0, h1);
        *(uint2*)(smem + SQ_LO + bOffT) = make_uint2(l0, l1);
    }
    cp16(aDst, asrc);
    cp16(aDst + 16, asrc + 8);
    asm volatile("cp.async.commit_group;" ::: "memory");

    float4 pb = okB ? *(const float4*)(bsrc + 32 + kq) : z4;

    for (int s = 0; s < NSTG; s++) {
        const int bufn = s & 1;
        asm volatile("cp.async.wait_group 0;" ::: "memory");
        __syncthreads();

        if (s + 1 < NSTG) {
            const int nb = bufn ^ 1;
            cp16(aDst + nb * 10240, asrc + (s + 1) * 32);
            cp16(aDst + nb * 10240 + 16, asrc + (s + 1) * 32 + 8);
            asm volatile("cp.async.commit_group;" ::: "memory");
            {
                uint32_t h0, l0, h1, l1;
                uint32_t off = nb * 5120 + bOffT;
                split2(pb.x, pb.y, h0, l0);
                split2(pb.z, pb.w, h1, l1);
                *(uint2*)(smem + B_HI + off) = make_uint2(h0, h1);
                *(uint2*)(smem + B_LO + off) = make_uint2(l0, l1);
                split2(pb.x * pb.x, pb.y * pb.y, h0, l0);
                split2(pb.z * pb.z, pb.w * pb.w, h1, l1);
                *(uint2*)(smem + SQ_HI + off) = make_uint2(h0, h1);
                *(uint2*)(smem + SQ_LO + off) = make_uint2(l0, l1);
            }
            if (s + 2 < NSTG)
                pb = okB ? *(const float4*)(bsrc + (s + 2) * 32 + kq) : z4;
        }

        const uint32_t aO = bufn * 10240u;
        const uint32_t bO = bufn * 5120u;
        #pragma unroll
        for (int su = 0; su < 2; su++) {
            uint32_t ah[2][4], al[2][4];
            #pragma unroll
            for (int mt = 0; mt < 2; mt++) {
                ldsm4(ah[mt], aB + aO + mt * 1280 + su * 32);
                ldsm4(al[mt], aB + aO + mt * 1280 + su * 32 + 20480);
            }
            uint32_t bh[2][2], bl[2][2];
            #pragma unroll
            for (int nt = 0; nt < 2; nt++) {
                ldsm2(bh[nt], bB + bO + nt * 640 + su * 32);
                ldsm2(bl[nt], bB + bO + nt * 640 + su * 32 + 10240);
            }
            #pragma unroll
            for (int mt = 0; mt < 2; mt++)
                #pragma unroll
                for (int nt = 0; nt < 2; nt++) {
                    mma16816(acc[mt][nt], ah[mt], bh[nt]);
                    mma16816(acc[mt][nt], ah[mt], bl[nt]);
                    mma16816(acc[mt][nt], al[mt], bh[nt]);
                }
            if (mi < 2) {
                const int t16 = 2 * s + su;
                uint32_t ivh[4], ivl[4], sh[2], sl[2];
                ldsm4(ivh, ivH + t16 * ivs);
                ldsm4(ivl, ivL + t16 * ivs);
                ldsm2(sh, sqB + bO + su * 32);
                ldsm2(sl, sqB + bO + su * 32 + 10240);
                mma16816(d2, ivh, sh);
                mma16816(d2, ivh, sl);
                mma16816(d2, ivl, sh);
            }
        }
    }

    // ---- epilogue ----
    const int r0  = lane >> 2;
    const int c0l = (lane & 3) * 2;
    float mx0 = -3.4e38f, mx1 = -3.4e38f;

    #pragma unroll
    for (int mt = 0; mt < 2; mt++) {
        const int mb = mi * 32 + mt * 16;
        #pragma unroll
        for (int nt = 0; nt < 2; nt++) {
            const int cg = n0 + ni * 16 + nt * 8 + c0l;
            if (cg >= NTOT) continue;
            const float* c = acc[mt][nt];
            const int m0 = mb + r0, m1 = m0 + 8;
            if (m0 < NM) {
                *(float2*)&g_S[(size_t)m0 * NTOT + cg] = make_float2(c[0], c[1]);
                if (m0 < BSZ) mx0 = fmaxf(mx0, fmaxf(c[0], c[1]));
            } else if (m0 < NM + NG) {
                g_SaaSam[cg * 10 + 5 + (m0 - NM)]       = c[0];
                g_SaaSam[(cg + 1) * 10 + 5 + (m0 - NM)] = c[1];
            }
            if (m1 < NM) {
                *(float2*)&g_S[(size_t)m1 * NTOT + cg] = make_float2(c[2], c[3]);
                if (m1 < BSZ) mx1 = fmaxf(mx1, fmaxf(c[2], c[3]));
            } else if (m1 < NM + NG) {
                g_SaaSam[cg * 10 + 5 + (m1 - NM)]       = c[2];
                g_SaaSam[(cg + 1) * 10 + 5 + (m1 - NM)] = c[3];
            }
        }
    }
    if (mi == 0) {
        if (r0 < BSZ)     atomicMax(&g_rowmax_u[r0], fenc(mx0));
        if (r0 + 8 < BSZ) atomicMax(&g_rowmax_u[r0 + 8], fenc(mx1));
    }
    if (mi < 2 && r0 < NG) {
        const int cg = n0 + tt * 8 + c0l;
        if (cg < NTOT) {
            g_SaaSam[cg * 10 + r0]       = d2[0];
            g_SaaSam[(cg + 1) * 10 + r0] = d2[1];
        }
    }
}

// ---------------------------------------------------------------------------
// K5: fused epilogue over all (b, n) cells
// ---------------------------------------------------------------------------
__global__ __launch_bounds__(256) void epi_kernel(const float* __restrict__ rank_mean,
                                                  float* __restrict__ out) {
    __shared__ float s_cnt[NG], s_sum[NG];
    const int tid = threadIdx.x;
    if (tid < NG) { s_cnt[tid] = 0.f; s_sum[tid] = 0.f; }
    __syncthreads();

    const int idx = blockIdx.x * 256 + tid;
    const int b = idx / NTOT;
    const int n = idx - b * NTOT;

    const float sim = g_S[b * NTOT + n];

    float lg[NG], ev[NG];
    #pragma unroll
    for (int g = 0; g < NG; g++) {
        float Sqa = g_S[(size_t)(BSZ + b * NG + g) * NTOT + n];
        float Saa = g_SaaSam[n * 10 + g];
        float Sam = g_SaaSam[n * 10 + 5 + g];
        lg[g] = g_Cbg[b * NG + g] + Sqa - 0.5f * Saa - Sam;
    }
    float m = lg[0]; int bi = 0;
    #pragma unroll
    for (int g = 1; g < NG; g++) if (lg[g] > m) { m = lg[g]; bi = g; }

    float sum = 0.f;
    #pragma unroll
    for (int g = 0; g < NG; g++) {
        float ln = lg[g] - m;
        out[OFF_GLOG + (size_t)idx * NG + g] = ln;
        float e = __expf(ln);
        ev[g] = e; sum += e;
    }
    float isum = 1.f / sum;
    #pragma unroll
    for (int g = 0; g < NG; g++)
        out[OFF_GPRB + (size_t)idx * NG + g] = ev[g] * isum;

    float bd = fabsf(sim - rank_mean[0]); int cp = 0;
    #pragma unroll
    for (int g = 1; g < NG; g++) {
        float d = fabsf(sim - rank_mean[g]);
        if (d < bd) { bd = d; cp = g; }
    }
    int cd = (int)floorf((sim + 1.0f) / 2.0f * 5.0f);

    bool golden = (n < BSZ) && (n == ((b + 8) & 15));
    bool eye    = (n == b);

    out[OFF_CLOG + idx] = sim - fdec(g_rowmax_u[b]);
    out[OFF_ACC  + idx] = eye ? 0.f : sim;
    out[OFF_GLBL + idx] = (float)((eye || golden) ? (NG - 1) : cp);
    out[OFF_CLBL + idx] = (float)(golden ? (NG - 1) : bi);
    out[OFF_CDST + idx] = (float)cd;

    atomicAdd(&s_cnt[bi], 1.f);
    atomicAdd(&s_sum[bi], sim);
    __syncthreads();
    if (tid < NG) {
        atomicAdd(&g_cnt[tid], s_cnt[tid]);
        atomicAdd(&g_sum[tid], s_sum[tid]);
    }
}

// ---------------------------------------------------------------------------
// K6: rank-mean EMA finalize
// ---------------------------------------------------------------------------
__global__ void finish_kernel(const float* __restrict__ rank_mean,
                              float* __restrict__ out) {
    int g = threadIdx.x;
    if (g < NG) {
        float c = g_cnt[g], s = g_sum[g];
        float cur = s / (c + 1e-12f);
        float upd = (c != 0.f) ? 1.f : 0.f;
        out[OFF_NRM + g] = (1.f - upd * 0.1f) * rank_mean[g] + upd * 0.1f * cur;
    }
}

// ---------------------------------------------------------------------------
extern "C" void kernel_launch(void* const* d_in, const int* in_sizes, int n_in,
                              void* d_out, int out_size) {
    const float* sent_q    = (const float*)d_in[0];
    const float* sent_k    = (const float*)d_in[1];
    const float* queue     = (const float*)d_in[2];
    const float* mu        = (const float*)d_in[3];
    const float* lg_sigma2 = (const float*)d_in[4];
    const float* pi        = (const float*)d_in[5];
    const float* rank_mean = (const float*)d_in[6];
    float* out = (float*)d_out;

    cudaFuncSetAttribute(gemm_mma_kernel,
                         cudaFuncAttributeMaxDynamicSharedMemorySize, SMTOT);

    inv_kernel<<<(NG * HD + 255) / 256, 256>>>(mu, lg_sigma2);
    w2_kernel<<<(128 * HD + 255) / 256, 256>>>(sent_q);
    cbg_kernel<<<10, 256>>>(sent_q, mu, lg_sigma2, pi);
    gemm_mma_kernel<<<(NTOT + 63) / 64, 512, SMTOT>>>(sent_k, queue);
    epi_kernel<<<(BSZ * NTOT) / 256, 256>>>(rank_mean, out);
    finish_kernel<<<1, 32>>>(rank_mean, out);
}